// round 1
// baseline (speedup 1.0000x reference)
#include <cuda_runtime.h>

#define HID 768
#define NH 12
#define HS 64
#define PATCH 512
#define SEQS 384              // B*M*NH = 8*4*12
#define ROWS 16384            // B*M*P = 8*4*512

// Scratch (device globals: the allowed no-alloc path)
__device__ float g_q[ROWS * HID];
__device__ float g_k[ROWS * HID];
__device__ float g_v[ROWS * HID];
__device__ float g_c[ROWS * HID];

// ---------------------------------------------------------------------------
// Fused QKV projection: out = hidden @ W + b, stored head-split:
// dst[((bm*NH + head)*PATCH + p)*HS + hh]
// Classic 128x128x8 SGEMM, 256 threads, 8x8 per thread.
// ---------------------------------------------------------------------------
__global__ __launch_bounds__(256, 2)
void qkv_gemm(const float* __restrict__ A,
              const float* __restrict__ Wq, const float* __restrict__ Wk,
              const float* __restrict__ Wv,
              const float* __restrict__ bq, const float* __restrict__ bk,
              const float* __restrict__ bv)
{
    __shared__ float As[8][132];   // padded: conflict-free transposed stores
    __shared__ float Bs[8][128];

    const int z = blockIdx.z;
    const float* W    = (z == 0) ? Wq : (z == 1) ? Wk : Wv;
    const float* bias = (z == 0) ? bq : (z == 1) ? bk : bv;
    float* dst        = (z == 0) ? g_q : (z == 1) ? g_k : g_v;

    const int m0 = blockIdx.x * 128;
    const int n0 = blockIdx.y * 128;
    const int t  = threadIdx.x;
    const int ty = t >> 4, tx = t & 15;

    const int arow = t >> 1,  ac4 = (t & 1) << 2;
    const int brow = t >> 5,  bc4 = (t & 31) << 2;

    const float* Aptr = A + (m0 + arow) * HID + ac4;
    const float* Wptr = W + brow * HID + n0 + bc4;

    float acc[8][8] = {};

    for (int k0 = 0; k0 < HID; k0 += 8) {
        float4 av = *(const float4*)(Aptr + k0);
        As[ac4 + 0][arow] = av.x;
        As[ac4 + 1][arow] = av.y;
        As[ac4 + 2][arow] = av.z;
        As[ac4 + 3][arow] = av.w;
        *(float4*)&Bs[brow][bc4] = *(const float4*)(Wptr + (long)k0 * HID);
        __syncthreads();
        #pragma unroll
        for (int kk = 0; kk < 8; kk++) {
            float a[8], b[8];
            *(float4*)&a[0] = *(float4*)&As[kk][ty * 8];
            *(float4*)&a[4] = *(float4*)&As[kk][ty * 8 + 4];
            *(float4*)&b[0] = *(float4*)&Bs[kk][tx * 8];
            *(float4*)&b[4] = *(float4*)&Bs[kk][tx * 8 + 4];
            #pragma unroll
            for (int i = 0; i < 8; i++)
                #pragma unroll
                for (int j = 0; j < 8; j++)
                    acc[i][j] += a[i] * b[j];
        }
        __syncthreads();
    }

    // epilogue with head-split remap; 8 consecutive cols never cross a head
    const int cn0  = n0 + tx * 8;
    const int head = cn0 >> 6;
    const int hh0  = cn0 & 63;
    float bvals[8];
    #pragma unroll
    for (int j = 0; j < 8; j++) bvals[j] = bias[cn0 + j];
    #pragma unroll
    for (int i = 0; i < 8; i++) {
        int rm = m0 + ty * 8 + i;
        int bm = rm >> 9;          // /512
        int p  = rm & 511;
        float* drow = dst + ((size_t)(bm * NH + head) * PATCH + p) * HS + hh0;
        float4 v0, v1;
        v0.x = acc[i][0] + bvals[0]; v0.y = acc[i][1] + bvals[1];
        v0.z = acc[i][2] + bvals[2]; v0.w = acc[i][3] + bvals[3];
        v1.x = acc[i][4] + bvals[4]; v1.y = acc[i][5] + bvals[5];
        v1.z = acc[i][6] + bvals[6]; v1.w = acc[i][7] + bvals[7];
        *(float4*)(drow)     = v0;
        *(float4*)(drow + 4) = v1;
    }
}

// ---------------------------------------------------------------------------
// Output projection: out = g_c @ Wo + bo (plain row-major store)
// ---------------------------------------------------------------------------
__global__ __launch_bounds__(256, 2)
void out_gemm(const float* __restrict__ W, const float* __restrict__ bias,
              float* __restrict__ out)
{
    __shared__ float As[8][132];
    __shared__ float Bs[8][128];

    const int m0 = blockIdx.x * 128;
    const int n0 = blockIdx.y * 128;
    const int t  = threadIdx.x;
    const int ty = t >> 4, tx = t & 15;

    const int arow = t >> 1,  ac4 = (t & 1) << 2;
    const int brow = t >> 5,  bc4 = (t & 31) << 2;

    const float* Aptr = g_c + (size_t)(m0 + arow) * HID + ac4;
    const float* Wptr = W + brow * HID + n0 + bc4;

    float acc[8][8] = {};

    for (int k0 = 0; k0 < HID; k0 += 8) {
        float4 av = *(const float4*)(Aptr + k0);
        As[ac4 + 0][arow] = av.x;
        As[ac4 + 1][arow] = av.y;
        As[ac4 + 2][arow] = av.z;
        As[ac4 + 3][arow] = av.w;
        *(float4*)&Bs[brow][bc4] = *(const float4*)(Wptr + (long)k0 * HID);
        __syncthreads();
        #pragma unroll
        for (int kk = 0; kk < 8; kk++) {
            float a[8], b[8];
            *(float4*)&a[0] = *(float4*)&As[kk][ty * 8];
            *(float4*)&a[4] = *(float4*)&As[kk][ty * 8 + 4];
            *(float4*)&b[0] = *(float4*)&Bs[kk][tx * 8];
            *(float4*)&b[4] = *(float4*)&Bs[kk][tx * 8 + 4];
            #pragma unroll
            for (int i = 0; i < 8; i++)
                #pragma unroll
                for (int j = 0; j < 8; j++)
                    acc[i][j] += a[i] * b[j];
        }
        __syncthreads();
    }

    const int cn0 = n0 + tx * 8;
    float bvals[8];
    #pragma unroll
    for (int j = 0; j < 8; j++) bvals[j] = bias[cn0 + j];
    #pragma unroll
    for (int i = 0; i < 8; i++) {
        int rm = m0 + ty * 8 + i;
        float* drow = out + (size_t)rm * HID + cn0;
        float4 v0, v1;
        v0.x = acc[i][0] + bvals[0]; v0.y = acc[i][1] + bvals[1];
        v0.z = acc[i][2] + bvals[2]; v0.w = acc[i][3] + bvals[3];
        v1.x = acc[i][4] + bvals[4]; v1.y = acc[i][5] + bvals[5];
        v1.z = acc[i][6] + bvals[6]; v1.w = acc[i][7] + bvals[7];
        *(float4*)(drow)     = v0;
        *(float4*)(drow + 4) = v1;
    }
}

// ---------------------------------------------------------------------------
// Flash-style attention. One block per (seq, 64-row q-tile).
// 256 threads as 16x16; each thread owns a 4x4 tile of S and of O.
// Online softmax with half-warp butterflies. hs = 64, kv tiles of 64.
// ---------------------------------------------------------------------------
#define ATT_SMEM ((3 * 4096 + 64 * 68 + 128) * 4)   // 67072 bytes

__global__ __launch_bounds__(256, 2)
void attn_kernel()
{
    extern __shared__ float sm[];
    float* Qt    = sm;               // [64][64] transposed (h-major)
    float* Kt    = Qt + 4096;        // [64][64] transposed
    float* Vs    = Kt + 4096;        // [64][64] direct
    float* Ps    = Vs + 4096;        // [64][68] padded
    float* row_m = Ps + 64 * 68;     // [64]
    float* row_l = row_m + 64;       // [64]

    const int seq = blockIdx.y;          // 0..383
    const int q0  = blockIdx.x * 64;
    const int t   = threadIdx.x;
    const int ty  = t >> 4, tx = t & 15;

    const float* qbase = g_q + ((size_t)seq * PATCH + q0) * HS;
    const float* kbase = g_k + (size_t)seq * PATCH * HS;
    const float* vbase = g_v + (size_t)seq * PATCH * HS;

    // Q load (transposed, pre-scaled by 1/sqrt(64))
    const float scale = 0.125f;
    for (int idx = t; idx < 64 * 16; idx += 256) {
        int i  = idx >> 4;
        int h4 = (idx & 15) << 2;
        float4 qv = *(const float4*)(qbase + i * HS + h4);
        Qt[(h4 + 0) * 64 + i] = qv.x * scale;
        Qt[(h4 + 1) * 64 + i] = qv.y * scale;
        Qt[(h4 + 2) * 64 + i] = qv.z * scale;
        Qt[(h4 + 3) * 64 + i] = qv.w * scale;
    }
    if (t < 64) { row_m[t] = -1e30f; row_l[t] = 0.0f; }

    float o[4][4] = {};

    for (int jt = 0; jt < 8; jt++) {
        __syncthreads();   // Q/stat init (iter 0) or prior P*V reads complete
        const float* kb = kbase + jt * 64 * HS;
        const float* vb = vbase + jt * 64 * HS;
        for (int idx = t; idx < 64 * 16; idx += 256) {
            int j  = idx >> 4;
            int h4 = (idx & 15) << 2;
            float4 kv = *(const float4*)(kb + j * HS + h4);
            Kt[(h4 + 0) * 64 + j] = kv.x;
            Kt[(h4 + 1) * 64 + j] = kv.y;
            Kt[(h4 + 2) * 64 + j] = kv.z;
            Kt[(h4 + 3) * 64 + j] = kv.w;
            float4 vv = *(const float4*)(vb + j * HS + h4);
            *(float4*)&Vs[j * 64 + h4] = vv;
        }
        __syncthreads();

        // S[i][j] = sum_h Qs[i][h] * Ks[j][h]
        float s[4][4] = {};
        #pragma unroll 16
        for (int h = 0; h < 64; h++) {
            float qa[4], kb4[4];
            *(float4*)qa  = *(float4*)&Qt[h * 64 + ty * 4];
            *(float4*)kb4 = *(float4*)&Kt[h * 64 + tx * 4];
            #pragma unroll
            for (int r = 0; r < 4; r++)
                #pragma unroll
                for (int c = 0; c < 4; c++)
                    s[r][c] += qa[r] * kb4[c];
        }

        // online softmax (rows split across 16 lanes of a half-warp)
        #pragma unroll
        for (int r = 0; r < 4; r++) {
            int i = ty * 4 + r;
            float lm = fmaxf(fmaxf(s[r][0], s[r][1]), fmaxf(s[r][2], s[r][3]));
            #pragma unroll
            for (int off = 8; off > 0; off >>= 1)
                lm = fmaxf(lm, __shfl_xor_sync(0xffffffffu, lm, off));
            float mold = row_m[i];
            float mnew = fmaxf(mold, lm);
            float f    = __expf(mold - mnew);
            float rs   = 0.0f;
            #pragma unroll
            for (int c = 0; c < 4; c++) {
                float pv = __expf(s[r][c] - mnew);
                rs += pv;
                Ps[i * 68 + tx * 4 + c] = pv;
            }
            #pragma unroll
            for (int off = 8; off > 0; off >>= 1)
                rs += __shfl_xor_sync(0xffffffffu, rs, off);
            if (tx == 0) { row_l[i] = row_l[i] * f + rs; row_m[i] = mnew; }
            #pragma unroll
            for (int c = 0; c < 4; c++) o[r][c] *= f;
        }
        __syncthreads();

        // O[i][h] += P[i][j] * V[j][h]
        #pragma unroll 8
        for (int j = 0; j < 64; j++) {
            float vb4[4];
            *(float4*)vb4 = *(float4*)&Vs[j * 64 + tx * 4];
            float a0 = Ps[(ty * 4 + 0) * 68 + j];
            float a1 = Ps[(ty * 4 + 1) * 68 + j];
            float a2 = Ps[(ty * 4 + 2) * 68 + j];
            float a3 = Ps[(ty * 4 + 3) * 68 + j];
            #pragma unroll
            for (int c = 0; c < 4; c++) {
                o[0][c] += a0 * vb4[c];
                o[1][c] += a1 * vb4[c];
                o[2][c] += a2 * vb4[c];
                o[3][c] += a3 * vb4[c];
            }
        }
    }

    // epilogue: normalize and write merged-head ctx
    const int bm = seq / NH, head = seq % NH;
    #pragma unroll
    for (int r = 0; r < 4; r++) {
        int i = ty * 4 + r;
        float inv = 1.0f / row_l[i];
        float4 ov;
        ov.x = o[r][0] * inv; ov.y = o[r][1] * inv;
        ov.z = o[r][2] * inv; ov.w = o[r][3] * inv;
        int row = bm * PATCH + q0 + i;
        *(float4*)&g_c[(size_t)row * HID + head * HS + tx * 4] = ov;
    }
}

// ---------------------------------------------------------------------------
extern "C" void kernel_launch(void* const* d_in, const int* in_sizes, int n_in,
                              void* d_out, int out_size)
{
    const float* hs = (const float*)d_in[0];
    const float* Wq = (const float*)d_in[1];
    const float* bq = (const float*)d_in[2];
    const float* Wk = (const float*)d_in[3];
    const float* bk = (const float*)d_in[4];
    const float* Wv = (const float*)d_in[5];
    const float* bv = (const float*)d_in[6];
    const float* Wo = (const float*)d_in[7];
    const float* bo = (const float*)d_in[8];
    float* out = (float*)d_out;

    cudaFuncSetAttribute(attn_kernel,
                         cudaFuncAttributeMaxDynamicSharedMemorySize, ATT_SMEM);

    qkv_gemm<<<dim3(128, 6, 3), 256>>>(hs, Wq, Wk, Wv, bq, bk, bv);
    attn_kernel<<<dim3(8, 384), 256, ATT_SMEM>>>();
    out_gemm<<<dim3(128, 6), 256>>>(Wo, bo, out);
}

// round 2
// speedup vs baseline: 1.8415x; 1.8415x over previous
#include <cuda_runtime.h>
#include <cstdint>

#define HID 768
#define NH 12
#define HS 64
#define PATCH 512
#define SEQS 384              // B*M*NH
#define ROWS 16384            // B*M*P

// Scratch (device globals: the allowed no-alloc path)
__device__ float g_q[ROWS * HID];
__device__ float g_k[ROWS * HID];
__device__ float g_v[ROWS * HID];
__device__ float g_c[ROWS * HID];

// ---------------------------------------------------------------------------
// tf32 helpers
// ---------------------------------------------------------------------------
__device__ __forceinline__ unsigned f2tf(float x) {
    unsigned r;
    asm("cvt.rna.tf32.f32 %0, %1;" : "=r"(r) : "f"(x));
    return r;
}

__device__ __forceinline__ void mma1688(float c[4],
                                        const unsigned a[4],
                                        const unsigned b[2]) {
    asm volatile(
        "mma.sync.aligned.m16n8k8.row.col.f32.tf32.tf32.f32 "
        "{%0,%1,%2,%3},{%4,%5,%6,%7},{%8,%9},{%0,%1,%2,%3};"
        : "+f"(c[0]), "+f"(c[1]), "+f"(c[2]), "+f"(c[3])
        : "r"(a[0]), "r"(a[1]), "r"(a[2]), "r"(a[3]), "r"(b[0]), "r"(b[1]));
}

// ---------------------------------------------------------------------------
// tf32 tensor-core GEMM: out = A @ W + b  (A: [16384, 768], W: [768, 768])
// 128x128x16 tiles, 8 warps (4x2), warp tile 32x64, m16n8k8 mma.
// headsplit=1: A=Aparam, dst picked from g_q/g_k/g_v by z, head-split store.
// headsplit=0: A=g_c, dst=dst_param, row-major store.
// ---------------------------------------------------------------------------
__global__ __launch_bounds__(256, 2)
void tf32_gemm(const float* __restrict__ Aparam,
               const float* __restrict__ W0, const float* __restrict__ W1,
               const float* __restrict__ W2,
               const float* __restrict__ bb0, const float* __restrict__ bb1,
               const float* __restrict__ bb2,
               float* __restrict__ dst_param, int headsplit)
{
    __shared__ unsigned As[2][128][20];   // [m][k] pad 20 -> conflict-free frags
    __shared__ unsigned Bs[2][16][132];   // [k][n] pad 132 -> conflict-free frags

    const int z = blockIdx.z;
    const float* W    = (z == 0) ? W0 : (z == 1) ? W1 : W2;
    const float* bias = (z == 0) ? bb0 : (z == 1) ? bb1 : bb2;
    const float* A    = headsplit ? Aparam : g_c;
    float* dst = dst_param;
    if (headsplit) dst = (z == 0) ? g_q : (z == 1) ? g_k : g_v;

    const int m0 = blockIdx.x * 128;
    const int n0 = blockIdx.y * 128;
    const int t    = threadIdx.x;
    const int warp = t >> 5, lane = t & 31;
    const int wm = (warp & 3) * 32;      // warp m offset within block tile
    const int wn = (warp >> 2) * 64;     // warp n offset

    // gmem load mapping
    const int ar = t >> 2, ac = (t & 3) << 2;       // A: 64 rows x 4 chunks
    const int br = t >> 5, bc = (t & 31) << 2;      // B: 8 rows x 32 chunks
    const float* Ap = A + (size_t)(m0 + ar) * HID + ac;
    const float* Wp = W + (size_t)br * HID + n0 + bc;

    float acc[2][8][4];
    #pragma unroll
    for (int i = 0; i < 2; i++)
        #pragma unroll
        for (int j = 0; j < 8; j++)
            #pragma unroll
            for (int l = 0; l < 4; l++) acc[i][j][l] = 0.0f;

    float4 pa0, pa1, pb0, pb1;

    // preload tile 0
    pa0 = *(const float4*)(Ap);
    pa1 = *(const float4*)(Ap + (size_t)64 * HID);
    pb0 = *(const float4*)(Wp);
    pb1 = *(const float4*)(Wp + (size_t)8 * HID);
    {
        uint4 u;
        u.x = f2tf(pa0.x); u.y = f2tf(pa0.y); u.z = f2tf(pa0.z); u.w = f2tf(pa0.w);
        *(uint4*)&As[0][ar][ac] = u;
        u.x = f2tf(pa1.x); u.y = f2tf(pa1.y); u.z = f2tf(pa1.z); u.w = f2tf(pa1.w);
        *(uint4*)&As[0][ar + 64][ac] = u;
        u.x = f2tf(pb0.x); u.y = f2tf(pb0.y); u.z = f2tf(pb0.z); u.w = f2tf(pb0.w);
        *(uint4*)&Bs[0][br][bc] = u;
        u.x = f2tf(pb1.x); u.y = f2tf(pb1.y); u.z = f2tf(pb1.z); u.w = f2tf(pb1.w);
        *(uint4*)&Bs[0][br + 8][bc] = u;
    }
    __syncthreads();

    int buf = 0;
    const int NIT = HID / 16;   // 48
    for (int it = 0; it < NIT; ++it) {
        if (it < NIT - 1) {
            const float* Ait = Ap + (it + 1) * 16;
            const float* Wit = Wp + (size_t)(it + 1) * 16 * HID;
            pa0 = *(const float4*)(Ait);
            pa1 = *(const float4*)(Ait + (size_t)64 * HID);
            pb0 = *(const float4*)(Wit);
            pb1 = *(const float4*)(Wit + (size_t)8 * HID);
        }

        // compute current buffer
        #pragma unroll
        for (int k8 = 0; k8 < 2; k8++) {
            unsigned afr[2][4], bfr[8][2];
            const int c = k8 * 8 + (lane & 3);
            #pragma unroll
            for (int mt = 0; mt < 2; mt++) {
                const int r = wm + mt * 16 + (lane >> 2);
                afr[mt][0] = As[buf][r][c];
                afr[mt][1] = As[buf][r + 8][c];
                afr[mt][2] = As[buf][r][c + 4];
                afr[mt][3] = As[buf][r + 8][c + 4];
            }
            #pragma unroll
            for (int nt = 0; nt < 8; nt++) {
                const int col = wn + nt * 8 + (lane >> 2);
                bfr[nt][0] = Bs[buf][c][col];
                bfr[nt][1] = Bs[buf][c + 4][col];
            }
            #pragma unroll
            for (int mt = 0; mt < 2; mt++)
                #pragma unroll
                for (int nt = 0; nt < 8; nt++)
                    mma1688(acc[mt][nt], afr[mt], bfr[nt]);
        }

        if (it < NIT - 1) {
            const int nb = buf ^ 1;
            uint4 u;
            u.x = f2tf(pa0.x); u.y = f2tf(pa0.y); u.z = f2tf(pa0.z); u.w = f2tf(pa0.w);
            *(uint4*)&As[nb][ar][ac] = u;
            u.x = f2tf(pa1.x); u.y = f2tf(pa1.y); u.z = f2tf(pa1.z); u.w = f2tf(pa1.w);
            *(uint4*)&As[nb][ar + 64][ac] = u;
            u.x = f2tf(pb0.x); u.y = f2tf(pb0.y); u.z = f2tf(pb0.z); u.w = f2tf(pb0.w);
            *(uint4*)&Bs[nb][br][bc] = u;
            u.x = f2tf(pb1.x); u.y = f2tf(pb1.y); u.z = f2tf(pb1.z); u.w = f2tf(pb1.w);
            *(uint4*)&Bs[nb][br + 8][bc] = u;
        }
        __syncthreads();
        buf ^= 1;
    }

    // epilogue
    #pragma unroll
    for (int mt = 0; mt < 2; mt++) {
        #pragma unroll
        for (int nt = 0; nt < 8; nt++) {
            const int row0 = m0 + wm + mt * 16 + (lane >> 2);
            const int col  = n0 + wn + nt * 8 + ((lane & 3) << 1);
            const float bv0 = bias[col];
            const float bv1 = bias[col + 1];
            float2 v0, v1;
            v0.x = acc[mt][nt][0] + bv0; v0.y = acc[mt][nt][1] + bv1;
            v1.x = acc[mt][nt][2] + bv0; v1.y = acc[mt][nt][3] + bv1;
            if (headsplit) {
                const int head = col >> 6, hh = col & 63;
                int bm = row0 >> 9, p = row0 & 511;
                *(float2*)&dst[((size_t)(bm * NH + head) * PATCH + p) * HS + hh] = v0;
                bm = (row0 + 8) >> 9; p = (row0 + 8) & 511;
                *(float2*)&dst[((size_t)(bm * NH + head) * PATCH + p) * HS + hh] = v1;
            } else {
                *(float2*)&dst[(size_t)row0 * HID + col] = v0;
                *(float2*)&dst[(size_t)(row0 + 8) * HID + col] = v1;
            }
        }
    }
}

// ---------------------------------------------------------------------------
// Flash-style attention (unchanged, fp32 FFMA). One block per (seq, q-tile 64).
// ---------------------------------------------------------------------------
#define ATT_SMEM ((3 * 4096 + 64 * 68 + 128) * 4)   // 67072 bytes

__global__ __launch_bounds__(256, 2)
void attn_kernel()
{
    extern __shared__ float sm[];
    float* Qt    = sm;               // [64][64] transposed (h-major)
    float* Kt    = Qt + 4096;        // [64][64] transposed
    float* Vs    = Kt + 4096;        // [64][64] direct
    float* Ps    = Vs + 4096;        // [64][68] padded
    float* row_m = Ps + 64 * 68;
    float* row_l = row_m + 64;

    const int seq = blockIdx.y;
    const int q0  = blockIdx.x * 64;
    const int t   = threadIdx.x;
    const int ty  = t >> 4, tx = t & 15;

    const float* qbase = g_q + ((size_t)seq * PATCH + q0) * HS;
    const float* kbase = g_k + (size_t)seq * PATCH * HS;
    const float* vbase = g_v + (size_t)seq * PATCH * HS;

    const float scale = 0.125f;
    for (int idx = t; idx < 64 * 16; idx += 256) {
        int i  = idx >> 4;
        int h4 = (idx & 15) << 2;
        float4 qv = *(const float4*)(qbase + i * HS + h4);
        Qt[(h4 + 0) * 64 + i] = qv.x * scale;
        Qt[(h4 + 1) * 64 + i] = qv.y * scale;
        Qt[(h4 + 2) * 64 + i] = qv.z * scale;
        Qt[(h4 + 3) * 64 + i] = qv.w * scale;
    }
    if (t < 64) { row_m[t] = -1e30f; row_l[t] = 0.0f; }

    float o[4][4] = {};

    for (int jt = 0; jt < 8; jt++) {
        __syncthreads();
        const float* kb = kbase + jt * 64 * HS;
        const float* vb = vbase + jt * 64 * HS;
        for (int idx = t; idx < 64 * 16; idx += 256) {
            int j  = idx >> 4;
            int h4 = (idx & 15) << 2;
            float4 kv = *(const float4*)(kb + j * HS + h4);
            Kt[(h4 + 0) * 64 + j] = kv.x;
            Kt[(h4 + 1) * 64 + j] = kv.y;
            Kt[(h4 + 2) * 64 + j] = kv.z;
            Kt[(h4 + 3) * 64 + j] = kv.w;
            float4 vv = *(const float4*)(vb + j * HS + h4);
            *(float4*)&Vs[j * 64 + h4] = vv;
        }
        __syncthreads();

        float s[4][4] = {};
        #pragma unroll 16
        for (int h = 0; h < 64; h++) {
            float qa[4], kb4[4];
            *(float4*)qa  = *(float4*)&Qt[h * 64 + ty * 4];
            *(float4*)kb4 = *(float4*)&Kt[h * 64 + tx * 4];
            #pragma unroll
            for (int r = 0; r < 4; r++)
                #pragma unroll
                for (int c = 0; c < 4; c++)
                    s[r][c] += qa[r] * kb4[c];
        }

        #pragma unroll
        for (int r = 0; r < 4; r++) {
            int i = ty * 4 + r;
            float lm = fmaxf(fmaxf(s[r][0], s[r][1]), fmaxf(s[r][2], s[r][3]));
            #pragma unroll
            for (int off = 8; off > 0; off >>= 1)
                lm = fmaxf(lm, __shfl_xor_sync(0xffffffffu, lm, off));
            float mold = row_m[i];
            float mnew = fmaxf(mold, lm);
            float f    = __expf(mold - mnew);
            float rs   = 0.0f;
            #pragma unroll
            for (int c = 0; c < 4; c++) {
                float pv = __expf(s[r][c] - mnew);
                rs += pv;
                Ps[i * 68 + tx * 4 + c] = pv;
            }
            #pragma unroll
            for (int off = 8; off > 0; off >>= 1)
                rs += __shfl_xor_sync(0xffffffffu, rs, off);
            if (tx == 0) { row_l[i] = row_l[i] * f + rs; row_m[i] = mnew; }
            #pragma unroll
            for (int c = 0; c < 4; c++) o[r][c] *= f;
        }
        __syncthreads();

        #pragma unroll 8
        for (int j = 0; j < 64; j++) {
            float vb4[4];
            *(float4*)vb4 = *(float4*)&Vs[j * 64 + tx * 4];
            float a0 = Ps[(ty * 4 + 0) * 68 + j];
            float a1 = Ps[(ty * 4 + 1) * 68 + j];
            float a2 = Ps[(ty * 4 + 2) * 68 + j];
            float a3 = Ps[(ty * 4 + 3) * 68 + j];
            #pragma unroll
            for (int c = 0; c < 4; c++) {
                o[0][c] += a0 * vb4[c];
                o[1][c] += a1 * vb4[c];
                o[2][c] += a2 * vb4[c];
                o[3][c] += a3 * vb4[c];
            }
        }
    }

    const int bm = seq / NH, head = seq % NH;
    #pragma unroll
    for (int r = 0; r < 4; r++) {
        int i = ty * 4 + r;
        float inv = 1.0f / row_l[i];
        float4 ov;
        ov.x = o[r][0] * inv; ov.y = o[r][1] * inv;
        ov.z = o[r][2] * inv; ov.w = o[r][3] * inv;
        int row = bm * PATCH + q0 + i;
        *(float4*)&g_c[(size_t)row * HID + head * HS + tx * 4] = ov;
    }
}

// ---------------------------------------------------------------------------
extern "C" void kernel_launch(void* const* d_in, const int* in_sizes, int n_in,
                              void* d_out, int out_size)
{
    const float* hs = (const float*)d_in[0];
    const float* Wq = (const float*)d_in[1];
    const float* bq = (const float*)d_in[2];
    const float* Wk = (const float*)d_in[3];
    const float* bk = (const float*)d_in[4];
    const float* Wv = (const float*)d_in[5];
    const float* bv = (const float*)d_in[6];
    const float* Wo = (const float*)d_in[7];
    const float* bo = (const float*)d_in[8];
    float* out = (float*)d_out;

    cudaFuncSetAttribute(attn_kernel,
                         cudaFuncAttributeMaxDynamicSharedMemorySize, ATT_SMEM);

    // QKV projections (z picks q/k/v)
    tf32_gemm<<<dim3(128, 6, 3), 256>>>(hs, Wq, Wk, Wv, bq, bk, bv,
                                        nullptr, 1);
    // attention
    attn_kernel<<<dim3(8, 384), 256, ATT_SMEM>>>();
    // output projection
    tf32_gemm<<<dim3(128, 6, 1), 256>>>(nullptr, Wo, Wo, Wo, bo, bo, bo,
                                        out, 0);
}

// round 4
// speedup vs baseline: 3.0210x; 1.6405x over previous
#include <cuda_runtime.h>
#include <cstdint>

#define HID 768
#define NH 12
#define HS 64
#define PATCH 512
#define SEQS 384              // B*M*NH
#define ROWS 16384            // B*M*P

// Scratch (device globals: the allowed no-alloc path)
__device__ float g_q[ROWS * HID];
__device__ float g_k[ROWS * HID];
__device__ float g_v[ROWS * HID];
__device__ float g_c[ROWS * HID];

// ---------------------------------------------------------------------------
// tf32 helpers
// ---------------------------------------------------------------------------
__device__ __forceinline__ unsigned f2tf(float x) {
    unsigned r;
    asm("cvt.rna.tf32.f32 %0, %1;" : "=r"(r) : "f"(x));
    return r;
}

__device__ __forceinline__ void mma1688(float c[4],
                                        const unsigned a[4],
                                        const unsigned b[2]) {
    asm volatile(
        "mma.sync.aligned.m16n8k8.row.col.f32.tf32.tf32.f32 "
        "{%0,%1,%2,%3},{%4,%5,%6,%7},{%8,%9},{%0,%1,%2,%3};"
        : "+f"(c[0]), "+f"(c[1]), "+f"(c[2]), "+f"(c[3])
        : "r"(a[0]), "r"(a[1]), "r"(a[2]), "r"(a[3]), "r"(b[0]), "r"(b[1]));
}

// ---------------------------------------------------------------------------
// tf32 tensor-core GEMM (unchanged from R2): out = A @ W + b
// ---------------------------------------------------------------------------
__global__ __launch_bounds__(256, 2)
void tf32_gemm(const float* __restrict__ Aparam,
               const float* __restrict__ W0, const float* __restrict__ W1,
               const float* __restrict__ W2,
               const float* __restrict__ bb0, const float* __restrict__ bb1,
               const float* __restrict__ bb2,
               float* __restrict__ dst_param, int headsplit)
{
    __shared__ unsigned As[2][128][20];
    __shared__ unsigned Bs[2][16][132];

    const int z = blockIdx.z;
    const float* W    = (z == 0) ? W0 : (z == 1) ? W1 : W2;
    const float* bias = (z == 0) ? bb0 : (z == 1) ? bb1 : bb2;
    const float* A    = headsplit ? Aparam : g_c;
    float* dst = dst_param;
    if (headsplit) dst = (z == 0) ? g_q : (z == 1) ? g_k : g_v;

    const int m0 = blockIdx.x * 128;
    const int n0 = blockIdx.y * 128;
    const int t    = threadIdx.x;
    const int warp = t >> 5, lane = t & 31;
    const int wm = (warp & 3) * 32;
    const int wn = (warp >> 2) * 64;

    const int ar = t >> 2, ac = (t & 3) << 2;
    const int br = t >> 5, bc = (t & 31) << 2;
    const float* Ap = A + (size_t)(m0 + ar) * HID + ac;
    const float* Wp = W + (size_t)br * HID + n0 + bc;

    float acc[2][8][4];
    #pragma unroll
    for (int i = 0; i < 2; i++)
        #pragma unroll
        for (int j = 0; j < 8; j++)
            #pragma unroll
            for (int l = 0; l < 4; l++) acc[i][j][l] = 0.0f;

    float4 pa0, pa1, pb0, pb1;
    pa0 = *(const float4*)(Ap);
    pa1 = *(const float4*)(Ap + (size_t)64 * HID);
    pb0 = *(const float4*)(Wp);
    pb1 = *(const float4*)(Wp + (size_t)8 * HID);
    {
        uint4 u;
        u.x = f2tf(pa0.x); u.y = f2tf(pa0.y); u.z = f2tf(pa0.z); u.w = f2tf(pa0.w);
        *(uint4*)&As[0][ar][ac] = u;
        u.x = f2tf(pa1.x); u.y = f2tf(pa1.y); u.z = f2tf(pa1.z); u.w = f2tf(pa1.w);
        *(uint4*)&As[0][ar + 64][ac] = u;
        u.x = f2tf(pb0.x); u.y = f2tf(pb0.y); u.z = f2tf(pb0.z); u.w = f2tf(pb0.w);
        *(uint4*)&Bs[0][br][bc] = u;
        u.x = f2tf(pb1.x); u.y = f2tf(pb1.y); u.z = f2tf(pb1.z); u.w = f2tf(pb1.w);
        *(uint4*)&Bs[0][br + 8][bc] = u;
    }
    __syncthreads();

    int buf = 0;
    const int NIT = HID / 16;
    for (int it = 0; it < NIT; ++it) {
        if (it < NIT - 1) {
            const float* Ait = Ap + (it + 1) * 16;
            const float* Wit = Wp + (size_t)(it + 1) * 16 * HID;
            pa0 = *(const float4*)(Ait);
            pa1 = *(const float4*)(Ait + (size_t)64 * HID);
            pb0 = *(const float4*)(Wit);
            pb1 = *(const float4*)(Wit + (size_t)8 * HID);
        }

        #pragma unroll
        for (int k8 = 0; k8 < 2; k8++) {
            unsigned afr[2][4], bfr[8][2];
            const int c = k8 * 8 + (lane & 3);
            #pragma unroll
            for (int mt = 0; mt < 2; mt++) {
                const int r = wm + mt * 16 + (lane >> 2);
                afr[mt][0] = As[buf][r][c];
                afr[mt][1] = As[buf][r + 8][c];
                afr[mt][2] = As[buf][r][c + 4];
                afr[mt][3] = As[buf][r + 8][c + 4];
            }
            #pragma unroll
            for (int nt = 0; nt < 8; nt++) {
                const int col = wn + nt * 8 + (lane >> 2);
                bfr[nt][0] = Bs[buf][c][col];
                bfr[nt][1] = Bs[buf][c + 4][col];
            }
            #pragma unroll
            for (int mt = 0; mt < 2; mt++)
                #pragma unroll
                for (int nt = 0; nt < 8; nt++)
                    mma1688(acc[mt][nt], afr[mt], bfr[nt]);
        }

        if (it < NIT - 1) {
            const int nb = buf ^ 1;
            uint4 u;
            u.x = f2tf(pa0.x); u.y = f2tf(pa0.y); u.z = f2tf(pa0.z); u.w = f2tf(pa0.w);
            *(uint4*)&As[nb][ar][ac] = u;
            u.x = f2tf(pa1.x); u.y = f2tf(pa1.y); u.z = f2tf(pa1.z); u.w = f2tf(pa1.w);
            *(uint4*)&As[nb][ar + 64][ac] = u;
            u.x = f2tf(pb0.x); u.y = f2tf(pb0.y); u.z = f2tf(pb0.z); u.w = f2tf(pb0.w);
            *(uint4*)&Bs[nb][br][bc] = u;
            u.x = f2tf(pb1.x); u.y = f2tf(pb1.y); u.z = f2tf(pb1.z); u.w = f2tf(pb1.w);
            *(uint4*)&Bs[nb][br + 8][bc] = u;
        }
        __syncthreads();
        buf ^= 1;
    }

    #pragma unroll
    for (int mt = 0; mt < 2; mt++) {
        #pragma unroll
        for (int nt = 0; nt < 8; nt++) {
            const int row0 = m0 + wm + mt * 16 + (lane >> 2);
            const int col  = n0 + wn + nt * 8 + ((lane & 3) << 1);
            const float bv0 = bias[col];
            const float bv1 = bias[col + 1];
            float2 v0, v1;
            v0.x = acc[mt][nt][0] + bv0; v0.y = acc[mt][nt][1] + bv1;
            v1.x = acc[mt][nt][2] + bv0; v1.y = acc[mt][nt][3] + bv1;
            if (headsplit) {
                const int head = col >> 6, hh = col & 63;
                int bm = row0 >> 9, p = row0 & 511;
                *(float2*)&dst[((size_t)(bm * NH + head) * PATCH + p) * HS + hh] = v0;
                bm = (row0 + 8) >> 9; p = (row0 + 8) & 511;
                *(float2*)&dst[((size_t)(bm * NH + head) * PATCH + p) * HS + hh] = v1;
            } else {
                *(float2*)&dst[(size_t)row0 * HID + col] = v0;
                *(float2*)&dst[(size_t)(row0 + 8) * HID + col] = v1;
            }
        }
    }
}

// ---------------------------------------------------------------------------
// Tensor-core flash attention (tf32 mma). 128 threads / 4 warps per block;
// warp w owns q-rows [16w, 16w+16). Smem pads chosen conflict-free:
//   K pad 68 (b-frag banks 4j+h distinct), V pad 72 (8j+h distinct),
//   P/Q pad 68 (a-frag banks 4i+c distinct).
// ---------------------------------------------------------------------------
#define KPAD 68
#define VPAD 72
#define PPAD 68
#define ATT_SMEM ((64 * KPAD + 64 * VPAD + 64 * PPAD) * 4)   // 53248 B

__device__ __forceinline__ void load_kv_tile(unsigned* Ks, unsigned* Vs,
                                             const float* kb, const float* vb,
                                             int t)
{
    #pragma unroll
    for (int i = 0; i < 8; i++) {
        int id = t + 128 * i;
        int r = id >> 4, c4 = (id & 15) << 2;
        float4 kv = *(const float4*)(kb + r * HS + c4);
        uint4 uk;
        uk.x = f2tf(kv.x); uk.y = f2tf(kv.y); uk.z = f2tf(kv.z); uk.w = f2tf(kv.w);
        *(uint4*)&Ks[r * KPAD + c4] = uk;
        float4 vv = *(const float4*)(vb + r * HS + c4);
        uint4 uv;
        uv.x = f2tf(vv.x); uv.y = f2tf(vv.y); uv.z = f2tf(vv.z); uv.w = f2tf(vv.w);
        *(uint4*)&Vs[r * VPAD + c4] = uv;
    }
}

__global__ __launch_bounds__(128, 3)
void attn_tc()
{
    extern __shared__ unsigned smem_u[];
    unsigned* Ks = smem_u;
    unsigned* Vs = Ks + 64 * KPAD;
    unsigned* Ps = Vs + 64 * VPAD;     // holds Q (prologue) then P (per tile)

    const int seq = blockIdx.y;
    const int q0  = blockIdx.x * 64;
    const int t    = threadIdx.x;
    const int warp = t >> 5, lane = t & 31;
    const int lq = lane >> 2;          // quad id 0..7
    const int lr = lane & 3;           // lane-in-quad

    const float* qbase = g_q + ((size_t)seq * PATCH + q0) * HS;
    const float* kbase = g_k + (size_t)seq * PATCH * HS;
    const float* vbase = g_v + (size_t)seq * PATCH * HS;

    // ---- stage Q (pre-scaled) into Ps as tf32 ----
    #pragma unroll
    for (int i = 0; i < 8; i++) {
        int id = t + 128 * i;
        int r = id >> 4, c4 = (id & 15) << 2;
        float4 qv = *(const float4*)(qbase + r * HS + c4);
        uint4 u;
        u.x = f2tf(qv.x * 0.125f); u.y = f2tf(qv.y * 0.125f);
        u.z = f2tf(qv.z * 0.125f); u.w = f2tf(qv.w * 0.125f);
        *(uint4*)&Ps[r * PPAD + c4] = u;
    }
    __syncthreads();

    // ---- Q fragments to registers (warp-private rows) ----
    const int rA = warp * 16 + lq;     // row A; row B = rA + 8
    unsigned qf[8][4];
    #pragma unroll
    for (int k8 = 0; k8 < 8; k8++) {
        const int c = k8 * 8 + lr;
        qf[k8][0] = Ps[rA * PPAD + c];
        qf[k8][1] = Ps[(rA + 8) * PPAD + c];
        qf[k8][2] = Ps[rA * PPAD + c + 4];
        qf[k8][3] = Ps[(rA + 8) * PPAD + c + 4];
    }
    // Ps is warp-private from here on (each warp rewrites only its own rows).

    float mA = -1e30f, mB = -1e30f, lA = 0.0f, lB = 0.0f;
    float o[8][4];
    #pragma unroll
    for (int nt = 0; nt < 8; nt++)
        #pragma unroll
        for (int j = 0; j < 4; j++) o[nt][j] = 0.0f;

    load_kv_tile(Ks, Vs, kbase, vbase, t);
    __syncthreads();

    for (int jt = 0; jt < 8; jt++) {
        // ---- S = Q K^T (rows A/B x 64 kv) ----
        float s[8][4];
        #pragma unroll
        for (int nt = 0; nt < 8; nt++)
            #pragma unroll
            for (int j = 0; j < 4; j++) s[nt][j] = 0.0f;

        #pragma unroll
        for (int k8 = 0; k8 < 8; k8++) {
            #pragma unroll
            for (int nt = 0; nt < 8; nt++) {
                unsigned b[2];
                const int col = nt * 8 + lq;
                b[0] = Ks[col * KPAD + k8 * 8 + lr];
                b[1] = Ks[col * KPAD + k8 * 8 + lr + 4];
                mma1688(s[nt], qf[k8], b);
            }
        }

        // ---- online softmax ----
        float tA = -1e30f, tB = -1e30f;
        #pragma unroll
        for (int nt = 0; nt < 8; nt++) {
            tA = fmaxf(tA, fmaxf(s[nt][0], s[nt][1]));
            tB = fmaxf(tB, fmaxf(s[nt][2], s[nt][3]));
        }
        tA = fmaxf(tA, __shfl_xor_sync(0xffffffffu, tA, 1));
        tA = fmaxf(tA, __shfl_xor_sync(0xffffffffu, tA, 2));
        tB = fmaxf(tB, __shfl_xor_sync(0xffffffffu, tB, 1));
        tB = fmaxf(tB, __shfl_xor_sync(0xffffffffu, tB, 2));
        const float nmA = fmaxf(mA, tA), nmB = fmaxf(mB, tB);
        const float fA = __expf(mA - nmA), fB = __expf(mB - nmB);
        mA = nmA; mB = nmB;

        float sumA = 0.0f, sumB = 0.0f;
        #pragma unroll
        for (int nt = 0; nt < 8; nt++) {
            const float p0 = __expf(s[nt][0] - mA);
            const float p1 = __expf(s[nt][1] - mA);
            const float p2 = __expf(s[nt][2] - mB);
            const float p3 = __expf(s[nt][3] - mB);
            sumA += p0 + p1;
            sumB += p2 + p3;
            uint2 uA; uA.x = f2tf(p0); uA.y = f2tf(p1);
            *(uint2*)&Ps[rA * PPAD + nt * 8 + 2 * lr] = uA;
            uint2 uB; uB.x = f2tf(p2); uB.y = f2tf(p3);
            *(uint2*)&Ps[(rA + 8) * PPAD + nt * 8 + 2 * lr] = uB;
        }
        sumA += __shfl_xor_sync(0xffffffffu, sumA, 1);
        sumA += __shfl_xor_sync(0xffffffffu, sumA, 2);
        sumB += __shfl_xor_sync(0xffffffffu, sumB, 1);
        sumB += __shfl_xor_sync(0xffffffffu, sumB, 2);
        lA = lA * fA + sumA;
        lB = lB * fB + sumB;
        #pragma unroll
        for (int nt = 0; nt < 8; nt++) {
            o[nt][0] *= fA; o[nt][1] *= fA;
            o[nt][2] *= fB; o[nt][3] *= fB;
        }
        __syncwarp();   // P visible across lanes of this warp

        // ---- O += P V ----
        #pragma unroll
        for (int k8 = 0; k8 < 8; k8++) {
            unsigned a[4];
            const int c = k8 * 8 + lr;
            a[0] = Ps[rA * PPAD + c];
            a[1] = Ps[(rA + 8) * PPAD + c];
            a[2] = Ps[rA * PPAD + c + 4];
            a[3] = Ps[(rA + 8) * PPAD + c + 4];
            #pragma unroll
            for (int nt = 0; nt < 8; nt++) {
                unsigned b[2];
                const int h = nt * 8 + lq;
                b[0] = Vs[(k8 * 8 + lr) * VPAD + h];
                b[1] = Vs[(k8 * 8 + lr + 4) * VPAD + h];
                mma1688(o[nt], a, b);
            }
        }

        if (jt < 7) {
            __syncthreads();    // all K/V reads of this tile done
            load_kv_tile(Ks, Vs, kbase + (jt + 1) * 64 * HS,
                         vbase + (jt + 1) * 64 * HS, t);
            __syncthreads();
        }
    }

    // ---- epilogue: normalize, write merged-head ctx ----
    const float invA = 1.0f / lA, invB = 1.0f / lB;
    const int bm = seq / NH, head = seq % NH;
    const int rowA = bm * PATCH + q0 + rA;
    float* dA = g_c + (size_t)rowA * HID + head * HS;
    float* dB = dA + (size_t)8 * HID;
    #pragma unroll
    for (int nt = 0; nt < 8; nt++) {
        float2 vA; vA.x = o[nt][0] * invA; vA.y = o[nt][1] * invA;
        *(float2*)&dA[nt * 8 + 2 * lr] = vA;
        float2 vB; vB.x = o[nt][2] * invB; vB.y = o[nt][3] * invB;
        *(float2*)&dB[nt * 8 + 2 * lr] = vB;
    }
}

// ---------------------------------------------------------------------------
extern "C" void kernel_launch(void* const* d_in, const int* in_sizes, int n_in,
                              void* d_out, int out_size)
{
    const float* hs = (const float*)d_in[0];
    const float* Wq = (const float*)d_in[1];
    const float* bq = (const float*)d_in[2];
    const float* Wk = (const float*)d_in[3];
    const float* bk = (const float*)d_in[4];
    const float* Wv = (const float*)d_in[5];
    const float* bv = (const float*)d_in[6];
    const float* Wo = (const float*)d_in[7];
    const float* bo = (const float*)d_in[8];
    float* out = (float*)d_out;

    cudaFuncSetAttribute(attn_tc,
                         cudaFuncAttributeMaxDynamicSharedMemorySize, ATT_SMEM);

    tf32_gemm<<<dim3(128, 6, 3), 256>>>(hs, Wq, Wk, Wv, bq, bk, bv,
                                        nullptr, 1);
    attn_tc<<<dim3(8, 384), 128, ATT_SMEM>>>();
    tf32_gemm<<<dim3(128, 6, 1), 256>>>(nullptr, Wo, Wo, Wo, bo, bo, bo,
                                        out, 0);
}

// round 5
// speedup vs baseline: 4.8827x; 1.6162x over previous
#include <cuda_runtime.h>
#include <cuda_fp16.h>
#include <cstdint>

#define HID 768
#define NH 12
#define HS 64
#define PATCH 512
#define SEQS 384              // B*M*NH
#define ROWS 16384            // B*M*P

// Scratch (device globals: the allowed no-alloc path)
__device__ float g_q[ROWS * HID];
__device__ float g_k[ROWS * HID];
__device__ float g_v[ROWS * HID];
__device__ float g_c[ROWS * HID];

// ---------------------------------------------------------------------------
// helpers
// ---------------------------------------------------------------------------
__device__ __forceinline__ unsigned f2tf(float x) {
    unsigned r;
    asm("cvt.rna.tf32.f32 %0, %1;" : "=r"(r) : "f"(x));
    return r;
}

__device__ __forceinline__ void mma1688(float c[4],
                                        const unsigned a[4],
                                        const unsigned b[2]) {
    asm volatile(
        "mma.sync.aligned.m16n8k8.row.col.f32.tf32.tf32.f32 "
        "{%0,%1,%2,%3},{%4,%5,%6,%7},{%8,%9},{%0,%1,%2,%3};"
        : "+f"(c[0]), "+f"(c[1]), "+f"(c[2]), "+f"(c[3])
        : "r"(a[0]), "r"(a[1]), "r"(a[2]), "r"(a[3]), "r"(b[0]), "r"(b[1]));
}

__device__ __forceinline__ void mma16816(float c[4],
                                         const unsigned a[4],
                                         const unsigned b[2]) {
    asm volatile(
        "mma.sync.aligned.m16n8k16.row.col.f32.f16.f16.f32 "
        "{%0,%1,%2,%3},{%4,%5,%6,%7},{%8,%9},{%0,%1,%2,%3};"
        : "+f"(c[0]), "+f"(c[1]), "+f"(c[2]), "+f"(c[3])
        : "r"(a[0]), "r"(a[1]), "r"(a[2]), "r"(a[3]), "r"(b[0]), "r"(b[1]));
}

__device__ __forceinline__ unsigned smem_u32(const void* p) {
    return (unsigned)__cvta_generic_to_shared(p);
}

__device__ __forceinline__ void ldsm4(unsigned& r0, unsigned& r1,
                                      unsigned& r2, unsigned& r3,
                                      unsigned addr) {
    asm volatile(
        "ldmatrix.sync.aligned.m8n8.x4.shared.b16 {%0,%1,%2,%3},[%4];"
        : "=r"(r0), "=r"(r1), "=r"(r2), "=r"(r3) : "r"(addr));
}

__device__ __forceinline__ void ldsm4t(unsigned& r0, unsigned& r1,
                                       unsigned& r2, unsigned& r3,
                                       unsigned addr) {
    asm volatile(
        "ldmatrix.sync.aligned.m8n8.x4.trans.shared.b16 {%0,%1,%2,%3},[%4];"
        : "=r"(r0), "=r"(r1), "=r"(r2), "=r"(r3) : "r"(addr));
}

__device__ __forceinline__ uint4 pack8(float4 a, float4 b) {
    uint4 u;
    __half2 h;
    h = __floats2half2_rn(a.x, a.y); u.x = *(unsigned*)&h;
    h = __floats2half2_rn(a.z, a.w); u.y = *(unsigned*)&h;
    h = __floats2half2_rn(b.x, b.y); u.z = *(unsigned*)&h;
    h = __floats2half2_rn(b.z, b.w); u.w = *(unsigned*)&h;
    return u;
}

// ---------------------------------------------------------------------------
// fp16 tensor-core GEMM: out = A @ W + b  (A:[16384,768] f32, W:[768,768] f32)
// 128x128x32 tiles, 8 warps (4x2), warp tile 32x64, m16n8k16, ldmatrix frags.
// A smem: [128 rows][4 x 16B units], swizzle unit^((row>>1)&3).
// B smem: [32 k-rows][16 x 16B units], swizzle unit^(k&7), loaded ldsm.trans.
// ---------------------------------------------------------------------------
#define BK 32

__global__ __launch_bounds__(256, 2)
void h_gemm(const float* __restrict__ Aparam,
            const float* __restrict__ W0, const float* __restrict__ W1,
            const float* __restrict__ W2,
            const float* __restrict__ bb0, const float* __restrict__ bb1,
            const float* __restrict__ bb2,
            float* __restrict__ dst_param, int headsplit)
{
    __shared__ uint4 As[2][128 * 4];
    __shared__ uint4 Bs[2][32 * 16];

    const int z = blockIdx.z;
    const float* W    = (z == 0) ? W0 : (z == 1) ? W1 : W2;
    const float* bias = (z == 0) ? bb0 : (z == 1) ? bb1 : bb2;
    const float* A    = headsplit ? Aparam : g_c;
    float* dst = dst_param;
    if (headsplit) dst = (z == 0) ? g_q : (z == 1) ? g_k : g_v;

    const int m0 = blockIdx.x * 128;
    const int n0 = blockIdx.y * 128;
    const int t    = threadIdx.x;
    const int warp = t >> 5, lane = t & 31;
    const int wm = (warp & 3) * 32;      // warp m offset
    const int wn = (warp >> 2) * 64;     // warp n offset
    const int wn8 = wn >> 3;

    // ---- gmem staging mapping ----
    // A: row r0 = t>>2 (and r0+64), unit ua = t&3 (8 floats each)
    const int r0 = t >> 2, ua = t & 3;
    const int suA = ua ^ ((r0 >> 1) & 3);          // same for r0 and r0+64
    const int aidx0 = r0 * 4 + suA;
    const int aidx1 = (r0 + 64) * 4 + suA;
    const float* ApA = A + (size_t)(m0 + r0) * HID + ua * 8;

    // B: k-row kr = t>>3, units ub and ub+8
    const int kr = t >> 3, ub = t & 7;
    const int bidx0 = kr * 16 + (ub ^ (kr & 7));
    const int bidx1 = bidx0 + 8;
    const float* WpB = W + (size_t)kr * HID + n0 + ub * 8;

    // ---- ldmatrix lane address components ----
    const int a_row  = wm + (lane & 7) + ((lane >> 3) & 1) * 8;  // + mt*16
    const int a_hi   = lane >> 4;                                 // unit half
    const int a_sw   = (a_row >> 1) & 3;     // invariant under +16 (mt)
    const int b_krow = (lane & 7) + ((lane >> 3) & 1) * 8;       // + s*16
    const int b_hi   = lane >> 4;
    const int b_sw   = lane & 7;             // = k&7, invariant under +8/+16

    const unsigned as_base = smem_u32(&As[0][0]);
    const unsigned bs_base = smem_u32(&Bs[0][0]);

    float acc[2][8][4];
    #pragma unroll
    for (int i = 0; i < 2; i++)
        #pragma unroll
        for (int j = 0; j < 8; j++)
            #pragma unroll
            for (int l = 0; l < 4; l++) acc[i][j][l] = 0.0f;

    // ---- stage iter 0 ----
    {
        float4 a0 = *(const float4*)(ApA);
        float4 a1 = *(const float4*)(ApA + 4);
        float4 a2 = *(const float4*)(ApA + (size_t)64 * HID);
        float4 a3 = *(const float4*)(ApA + (size_t)64 * HID + 4);
        As[0][aidx0] = pack8(a0, a1);
        As[0][aidx1] = pack8(a2, a3);
        float4 b0 = *(const float4*)(WpB);
        float4 b1 = *(const float4*)(WpB + 4);
        float4 b2 = *(const float4*)(WpB + 64);
        float4 b3 = *(const float4*)(WpB + 68);
        Bs[0][bidx0] = pack8(b0, b1);
        Bs[0][bidx1] = pack8(b2, b3);
    }
    __syncthreads();

    int buf = 0;
    const int NIT = HID / BK;    // 24
    float4 pa0, pa1, pa2, pa3, pb0, pb1, pb2, pb3;

    for (int it = 0; it < NIT; ++it) {
        if (it < NIT - 1) {
            const float* Ait = ApA + (it + 1) * BK;
            const float* Wit = WpB + (size_t)(it + 1) * BK * HID;
            pa0 = *(const float4*)(Ait);
            pa1 = *(const float4*)(Ait + 4);
            pa2 = *(const float4*)(Ait + (size_t)64 * HID);
            pa3 = *(const float4*)(Ait + (size_t)64 * HID + 4);
            pb0 = *(const float4*)(Wit);
            pb1 = *(const float4*)(Wit + 4);
            pb2 = *(const float4*)(Wit + 64);
            pb3 = *(const float4*)(Wit + 68);
        }

        const unsigned abuf = as_base + buf * (128 * 4 * 16);
        const unsigned bbuf = bs_base + buf * (32 * 16 * 16);

        #pragma unroll
        for (int s = 0; s < 2; s++) {
            unsigned af[2][4];
            #pragma unroll
            for (int mt = 0; mt < 2; mt++) {
                const unsigned addr = abuf +
                    (((a_row + mt * 16) * 4 + ((s * 2 + a_hi) ^ a_sw)) << 4);
                ldsm4(af[mt][0], af[mt][1], af[mt][2], af[mt][3], addr);
            }
            unsigned bf[8][2];
            #pragma unroll
            for (int ntp = 0; ntp < 8; ntp += 2) {
                const unsigned addr = bbuf +
                    (((s * 16 + b_krow) * 16 +
                      ((wn8 + ntp + b_hi) ^ b_sw)) << 4);
                ldsm4t(bf[ntp][0], bf[ntp][1], bf[ntp + 1][0], bf[ntp + 1][1],
                       addr);
            }
            #pragma unroll
            for (int mt = 0; mt < 2; mt++)
                #pragma unroll
                for (int nt = 0; nt < 8; nt++)
                    mma16816(acc[mt][nt], af[mt], bf[nt]);
        }

        if (it < NIT - 1) {
            const int nb = buf ^ 1;
            As[nb][aidx0] = pack8(pa0, pa1);
            As[nb][aidx1] = pack8(pa2, pa3);
            Bs[nb][bidx0] = pack8(pb0, pb1);
            Bs[nb][bidx1] = pack8(pb2, pb3);
        }
        __syncthreads();
        buf ^= 1;
    }

    // ---- epilogue (C frag: c0,c1 at (lq, 2lr..), c2,c3 at (lq+8, 2lr..)) ----
    #pragma unroll
    for (int mt = 0; mt < 2; mt++) {
        #pragma unroll
        for (int nt = 0; nt < 8; nt++) {
            const int row0 = m0 + wm + mt * 16 + (lane >> 2);
            const int col  = n0 + wn + nt * 8 + ((lane & 3) << 1);
            const float bv0 = bias[col];
            const float bv1 = bias[col + 1];
            float2 v0, v1;
            v0.x = acc[mt][nt][0] + bv0; v0.y = acc[mt][nt][1] + bv1;
            v1.x = acc[mt][nt][2] + bv0; v1.y = acc[mt][nt][3] + bv1;
            if (headsplit) {
                const int head = col >> 6, hh = col & 63;
                int bm = row0 >> 9, p = row0 & 511;
                *(float2*)&dst[((size_t)(bm * NH + head) * PATCH + p) * HS + hh] = v0;
                bm = (row0 + 8) >> 9; p = (row0 + 8) & 511;
                *(float2*)&dst[((size_t)(bm * NH + head) * PATCH + p) * HS + hh] = v1;
            } else {
                *(float2*)&dst[(size_t)row0 * HID + col] = v0;
                *(float2*)&dst[(size_t)(row0 + 8) * HID + col] = v1;
            }
        }
    }
}

// ---------------------------------------------------------------------------
// Tensor-core flash attention (tf32 mma) — unchanged from R3 (known good).
// ---------------------------------------------------------------------------
#define KPAD 68
#define VPAD 72
#define PPAD 68
#define ATT_SMEM ((64 * KPAD + 64 * VPAD + 64 * PPAD) * 4)   // 53248 B

__device__ __forceinline__ void load_kv_tile(unsigned* Ks, unsigned* Vs,
                                             const float* kb, const float* vb,
                                             int t)
{
    #pragma unroll
    for (int i = 0; i < 8; i++) {
        int id = t + 128 * i;
        int r = id >> 4, c4 = (id & 15) << 2;
        float4 kv = *(const float4*)(kb + r * HS + c4);
        uint4 uk;
        uk.x = f2tf(kv.x); uk.y = f2tf(kv.y); uk.z = f2tf(kv.z); uk.w = f2tf(kv.w);
        *(uint4*)&Ks[r * KPAD + c4] = uk;
        float4 vv = *(const float4*)(vb + r * HS + c4);
        uint4 uv;
        uv.x = f2tf(vv.x); uv.y = f2tf(vv.y); uv.z = f2tf(vv.z); uv.w = f2tf(vv.w);
        *(uint4*)&Vs[r * VPAD + c4] = uv;
    }
}

__global__ __launch_bounds__(128, 3)
void attn_tc()
{
    extern __shared__ unsigned smem_u[];
    unsigned* Ks = smem_u;
    unsigned* Vs = Ks + 64 * KPAD;
    unsigned* Ps = Vs + 64 * VPAD;

    const int seq = blockIdx.y;
    const int q0  = blockIdx.x * 64;
    const int t    = threadIdx.x;
    const int warp = t >> 5, lane = t & 31;
    const int lq = lane >> 2;
    const int lr = lane & 3;

    const float* qbase = g_q + ((size_t)seq * PATCH + q0) * HS;
    const float* kbase = g_k + (size_t)seq * PATCH * HS;
    const float* vbase = g_v + (size_t)seq * PATCH * HS;

    #pragma unroll
    for (int i = 0; i < 8; i++) {
        int id = t + 128 * i;
        int r = id >> 4, c4 = (id & 15) << 2;
        float4 qv = *(const float4*)(qbase + r * HS + c4);
        uint4 u;
        u.x = f2tf(qv.x * 0.125f); u.y = f2tf(qv.y * 0.125f);
        u.z = f2tf(qv.z * 0.125f); u.w = f2tf(qv.w * 0.125f);
        *(uint4*)&Ps[r * PPAD + c4] = u;
    }
    __syncthreads();

    const int rA = warp * 16 + lq;
    unsigned qf[8][4];
    #pragma unroll
    for (int k8 = 0; k8 < 8; k8++) {
        const int c = k8 * 8 + lr;
        qf[k8][0] = Ps[rA * PPAD + c];
        qf[k8][1] = Ps[(rA + 8) * PPAD + c];
        qf[k8][2] = Ps[rA * PPAD + c + 4];
        qf[k8][3] = Ps[(rA + 8) * PPAD + c + 4];
    }

    float mA = -1e30f, mB = -1e30f, lA = 0.0f, lB = 0.0f;
    float o[8][4];
    #pragma unroll
    for (int nt = 0; nt < 8; nt++)
        #pragma unroll
        for (int j = 0; j < 4; j++) o[nt][j] = 0.0f;

    load_kv_tile(Ks, Vs, kbase, vbase, t);
    __syncthreads();

    for (int jt = 0; jt < 8; jt++) {
        float s[8][4];
        #pragma unroll
        for (int nt = 0; nt < 8; nt++)
            #pragma unroll
            for (int j = 0; j < 4; j++) s[nt][j] = 0.0f;

        #pragma unroll
        for (int k8 = 0; k8 < 8; k8++) {
            #pragma unroll
            for (int nt = 0; nt < 8; nt++) {
                unsigned b[2];
                const int col = nt * 8 + lq;
                b[0] = Ks[col * KPAD + k8 * 8 + lr];
                b[1] = Ks[col * KPAD + k8 * 8 + lr + 4];
                mma1688(s[nt], qf[k8], b);
            }
        }

        float tA = -1e30f, tB = -1e30f;
        #pragma unroll
        for (int nt = 0; nt < 8; nt++) {
            tA = fmaxf(tA, fmaxf(s[nt][0], s[nt][1]));
            tB = fmaxf(tB, fmaxf(s[nt][2], s[nt][3]));
        }
        tA = fmaxf(tA, __shfl_xor_sync(0xffffffffu, tA, 1));
        tA = fmaxf(tA, __shfl_xor_sync(0xffffffffu, tA, 2));
        tB = fmaxf(tB, __shfl_xor_sync(0xffffffffu, tB, 1));
        tB = fmaxf(tB, __shfl_xor_sync(0xffffffffu, tB, 2));
        const float nmA = fmaxf(mA, tA), nmB = fmaxf(mB, tB);
        const float fA = __expf(mA - nmA), fB = __expf(mB - nmB);
        mA = nmA; mB = nmB;

        float sumA = 0.0f, sumB = 0.0f;
        #pragma unroll
        for (int nt = 0; nt < 8; nt++) {
            const float p0 = __expf(s[nt][0] - mA);
            const float p1 = __expf(s[nt][1] - mA);
            const float p2 = __expf(s[nt][2] - mB);
            const float p3 = __expf(s[nt][3] - mB);
            sumA += p0 + p1;
            sumB += p2 + p3;
            uint2 uA; uA.x = f2tf(p0); uA.y = f2tf(p1);
            *(uint2*)&Ps[rA * PPAD + nt * 8 + 2 * lr] = uA;
            uint2 uB; uB.x = f2tf(p2); uB.y = f2tf(p3);
            *(uint2*)&Ps[(rA + 8) * PPAD + nt * 8 + 2 * lr] = uB;
        }
        sumA += __shfl_xor_sync(0xffffffffu, sumA, 1);
        sumA += __shfl_xor_sync(0xffffffffu, sumA, 2);
        sumB += __shfl_xor_sync(0xffffffffu, sumB, 1);
        sumB += __shfl_xor_sync(0xffffffffu, sumB, 2);
        lA = lA * fA + sumA;
        lB = lB * fB + sumB;
        #pragma unroll
        for (int nt = 0; nt < 8; nt++) {
            o[nt][0] *= fA; o[nt][1] *= fA;
            o[nt][2] *= fB; o[nt][3] *= fB;
        }
        __syncwarp();

        #pragma unroll
        for (int k8 = 0; k8 < 8; k8++) {
            unsigned a[4];
            const int c = k8 * 8 + lr;
            a[0] = Ps[rA * PPAD + c];
            a[1] = Ps[(rA + 8) * PPAD + c];
            a[2] = Ps[rA * PPAD + c + 4];
            a[3] = Ps[(rA + 8) * PPAD + c + 4];
            #pragma unroll
            for (int nt = 0; nt < 8; nt++) {
                unsigned b[2];
                const int h = nt * 8 + lq;
                b[0] = Vs[(k8 * 8 + lr) * VPAD + h];
                b[1] = Vs[(k8 * 8 + lr + 4) * VPAD + h];
                mma1688(o[nt], a, b);
            }
        }

        if (jt < 7) {
            __syncthreads();
            load_kv_tile(Ks, Vs, kbase + (jt + 1) * 64 * HS,
                         vbase + (jt + 1) * 64 * HS, t);
            __syncthreads();
        }
    }

    const float invA = 1.0f / lA, invB = 1.0f / lB;
    const int bm = seq / NH, head = seq % NH;
    const int rowA = bm * PATCH + q0 + rA;
    float* dA = g_c + (size_t)rowA * HID + head * HS;
    float* dB = dA + (size_t)8 * HID;
    #pragma unroll
    for (int nt = 0; nt < 8; nt++) {
        float2 vA; vA.x = o[nt][0] * invA; vA.y = o[nt][1] * invA;
        *(float2*)&dA[nt * 8 + 2 * lr] = vA;
        float2 vB; vB.x = o[nt][2] * invB; vB.y = o[nt][3] * invB;
        *(float2*)&dB[nt * 8 + 2 * lr] = vB;
    }
}

// ---------------------------------------------------------------------------
extern "C" void kernel_launch(void* const* d_in, const int* in_sizes, int n_in,
                              void* d_out, int out_size)
{
    const float* hs = (const float*)d_in[0];
    const float* Wq = (const float*)d_in[1];
    const float* bq = (const float*)d_in[2];
    const float* Wk = (const float*)d_in[3];
    const float* bk = (const float*)d_in[4];
    const float* Wv = (const float*)d_in[5];
    const float* bv = (const float*)d_in[6];
    const float* Wo = (const float*)d_in[7];
    const float* bo = (const float*)d_in[8];
    float* out = (float*)d_out;

    cudaFuncSetAttribute(attn_tc,
                         cudaFuncAttributeMaxDynamicSharedMemorySize, ATT_SMEM);

    h_gemm<<<dim3(128, 6, 3), 256>>>(hs, Wq, Wk, Wv, bq, bk, bv,
                                     nullptr, 1);
    attn_tc<<<dim3(8, 384), 128, ATT_SMEM>>>();
    h_gemm<<<dim3(128, 6, 1), 256>>>(nullptr, Wo, Wo, Wo, bo, bo, bo,
                                     out, 0);
}

// round 6
// speedup vs baseline: 5.8728x; 1.2028x over previous
#include <cuda_runtime.h>
#include <cuda_fp16.h>
#include <cstdint>

#define HID 768
#define NH 12
#define HS 64
#define PATCH 512
#define SEQS 384              // B*M*NH
#define ROWS 16384            // B*M*P
#define BK 32

// fp16 scratch (device globals: the allowed no-alloc path)
__device__ __half g_h16[ROWS * HID];
__device__ __half g_w16[4][HID * HID];
__device__ __half g_q16[ROWS * HID];
__device__ __half g_k16[ROWS * HID];
__device__ __half g_v16[ROWS * HID];
__device__ __half g_c16[ROWS * HID];

// ---------------------------------------------------------------------------
// helpers
// ---------------------------------------------------------------------------
__device__ __forceinline__ void mma16816(float c[4],
                                         const unsigned a[4],
                                         const unsigned b[2]) {
    asm volatile(
        "mma.sync.aligned.m16n8k16.row.col.f32.f16.f16.f32 "
        "{%0,%1,%2,%3},{%4,%5,%6,%7},{%8,%9},{%0,%1,%2,%3};"
        : "+f"(c[0]), "+f"(c[1]), "+f"(c[2]), "+f"(c[3])
        : "r"(a[0]), "r"(a[1]), "r"(a[2]), "r"(a[3]), "r"(b[0]), "r"(b[1]));
}

__device__ __forceinline__ unsigned smem_u32(const void* p) {
    return (unsigned)__cvta_generic_to_shared(p);
}

__device__ __forceinline__ void ldsm4(unsigned& r0, unsigned& r1,
                                      unsigned& r2, unsigned& r3,
                                      unsigned addr) {
    asm volatile(
        "ldmatrix.sync.aligned.m8n8.x4.shared.b16 {%0,%1,%2,%3},[%4];"
        : "=r"(r0), "=r"(r1), "=r"(r2), "=r"(r3) : "r"(addr));
}

__device__ __forceinline__ void ldsm4t(unsigned& r0, unsigned& r1,
                                       unsigned& r2, unsigned& r3,
                                       unsigned addr) {
    asm volatile(
        "ldmatrix.sync.aligned.m8n8.x4.trans.shared.b16 {%0,%1,%2,%3},[%4];"
        : "=r"(r0), "=r"(r1), "=r"(r2), "=r"(r3) : "r"(addr));
}

// ---------------------------------------------------------------------------
// Prologue: convert hidden + 4 weight matrices to fp16 (single launch)
// ---------------------------------------------------------------------------
__global__ void cvt_all(const float* __restrict__ hs,
                        const float* __restrict__ Wq,
                        const float* __restrict__ Wk,
                        const float* __restrict__ Wv,
                        const float* __restrict__ Wo)
{
    const int i = blockIdx.x * blockDim.x + threadIdx.x;   // float4 index
    const int nh4 = ROWS * HID / 4;
    if (i < nh4) {
        float4 v = ((const float4*)hs)[i];
        __half2 h0 = __floats2half2_rn(v.x, v.y);
        __half2 h1 = __floats2half2_rn(v.z, v.w);
        uint2 u; u.x = *(unsigned*)&h0; u.y = *(unsigned*)&h1;
        ((uint2*)g_h16)[i] = u;
    }
    const int nw4 = HID * HID / 4;
    if (i < nw4) {
        const float* srcs[4] = {Wq, Wk, Wv, Wo};
        #pragma unroll
        for (int z = 0; z < 4; z++) {
            float4 v = ((const float4*)srcs[z])[i];
            __half2 h0 = __floats2half2_rn(v.x, v.y);
            __half2 h1 = __floats2half2_rn(v.z, v.w);
            uint2 u; u.x = *(unsigned*)&h0; u.y = *(unsigned*)&h1;
            ((uint2*)g_w16[z])[i] = u;
        }
    }
}

// ---------------------------------------------------------------------------
// fp16-in fp32-acc GEMM: out = A16 @ W16 + b
// 128x128x32 tiles, 8 warps (4x2), warp tile 32x64, m16n8k16, ldmatrix frags.
// A smem: 64 super-rows (2 m-rows each) x 8 units(16B), swizzle u^(sr&7).
// B smem: 32 k-rows x 16 units, swizzle u^(k&7), read via ldsm4t.
// headsplit=1: A=g_h16, W/bias by z, dst = g_{q,k,v}16 head-split fp16.
// headsplit=0: A=g_c16, W slice 3, dst = outf fp32 row-major.
// ---------------------------------------------------------------------------
__global__ __launch_bounds__(256, 2)
void h16_gemm(const float* __restrict__ bq, const float* __restrict__ bk,
              const float* __restrict__ bv, const float* __restrict__ bo,
              float* __restrict__ outf, int headsplit)
{
    __shared__ uint4 As[2][64 * 8];
    __shared__ uint4 Bs[2][32 * 16];

    const int z = blockIdx.z;
    const __half* A = headsplit ? g_h16 : g_c16;
    const __half* W = g_w16[headsplit ? z : 3];
    const float* bias = headsplit ? (z == 0 ? bq : z == 1 ? bk : bv) : bo;
    __half* dsth = (z == 0) ? g_q16 : (z == 1) ? g_k16 : g_v16;

    const int m0 = blockIdx.x * 128;
    const int n0 = blockIdx.y * 128;
    const int t = threadIdx.x;
    const int warp = t >> 5, lane = t & 31;
    const int wm = (warp & 3) * 32;
    const int wn = (warp >> 2) * 64;
    const int wn8 = wn >> 3;                     // n-unit base (8 halves/unit)

    // ---- gmem staging mapping (2x 16B per thread for each of A,B) ----
    const int ar   = t >> 1;                     // A row 0..127
    const int aku  = (t & 1) * 2;                // first of 2 k-units
    const int asr  = ar >> 1;
    const int abase = (ar & 1) * 4;
    const int aidx0 = asr * 8 + ((abase + aku) ^ (asr & 7));
    const int aidx1 = asr * 8 + ((abase + aku + 1) ^ (asr & 7));
    const __half* Ap = A + (size_t)(m0 + ar) * HID + aku * 8;

    const int bkr  = t >> 3;                     // B k-row 0..31
    const int bun  = (t & 7) * 2;
    const int bidx0 = bkr * 16 + (bun ^ (bkr & 7));
    const int bidx1 = bkr * 16 + ((bun + 1) ^ (bkr & 7));
    const __half* Wp = W + (size_t)bkr * HID + n0 + bun * 8;

    // ---- ldmatrix lane components ----
    const int a_m   = wm + (lane & 7) + ((lane >> 3) & 1) * 8;  // +mt*16
    const int a_sr  = a_m >> 1;                  // +mt*8 (sr&7 invariant)
    const int a_sw  = a_sr & 7;
    const int a_bse = (a_m & 1) * 4;
    const int a_hi  = lane >> 4;
    const int b_krow = (lane & 7) + ((lane >> 3) & 1) * 8;      // +s*16
    const int b_hi   = lane >> 4;
    const int b_sw   = lane & 7;

    const unsigned as_base = smem_u32(&As[0][0]);
    const unsigned bs_base = smem_u32(&Bs[0][0]);

    float acc[2][8][4];
    #pragma unroll
    for (int i = 0; i < 2; i++)
        #pragma unroll
        for (int j = 0; j < 8; j++)
            #pragma unroll
            for (int l = 0; l < 4; l++) acc[i][j][l] = 0.0f;

    // ---- stage iter 0 ----
    As[0][aidx0] = *(const uint4*)(Ap);
    As[0][aidx1] = *(const uint4*)(Ap + 8);
    Bs[0][bidx0] = *(const uint4*)(Wp);
    Bs[0][bidx1] = *(const uint4*)(Wp + 8);
    __syncthreads();

    int buf = 0;
    const int NIT = HID / BK;      // 24
    uint4 pa0, pa1, pb0, pb1;

    for (int it = 0; it < NIT; ++it) {
        if (it < NIT - 1) {
            const __half* Ait = Ap + (it + 1) * BK;
            const __half* Wit = Wp + (size_t)(it + 1) * BK * HID;
            pa0 = *(const uint4*)(Ait);
            pa1 = *(const uint4*)(Ait + 8);
            pb0 = *(const uint4*)(Wit);
            pb1 = *(const uint4*)(Wit + 8);
        }

        const unsigned abuf = as_base + buf * (64 * 8 * 16);
        const unsigned bbuf = bs_base + buf * (32 * 16 * 16);

        #pragma unroll
        for (int s = 0; s < 2; s++) {
            unsigned af[2][4];
            #pragma unroll
            for (int mt = 0; mt < 2; mt++) {
                const int sr = a_sr + mt * 8;
                const unsigned addr = abuf +
                    ((sr * 8 + ((a_bse + s * 2 + a_hi) ^ a_sw)) << 4);
                ldsm4(af[mt][0], af[mt][1], af[mt][2], af[mt][3], addr);
            }
            unsigned bf[8][2];
            #pragma unroll
            for (int ntp = 0; ntp < 8; ntp += 2) {
                const int row = s * 16 + b_krow;
                const unsigned addr = bbuf +
                    ((row * 16 + ((wn8 + ntp + b_hi) ^ b_sw)) << 4);
                ldsm4t(bf[ntp][0], bf[ntp][1], bf[ntp + 1][0], bf[ntp + 1][1],
                       addr);
            }
            #pragma unroll
            for (int mt = 0; mt < 2; mt++)
                #pragma unroll
                for (int nt = 0; nt < 8; nt++)
                    mma16816(acc[mt][nt], af[mt], bf[nt]);
        }

        if (it < NIT - 1) {
            const int nb = buf ^ 1;
            As[nb][aidx0] = pa0;
            As[nb][aidx1] = pa1;
            Bs[nb][bidx0] = pb0;
            Bs[nb][bidx1] = pb1;
        }
        __syncthreads();
        buf ^= 1;
    }

    // ---- epilogue ----
    #pragma unroll
    for (int mt = 0; mt < 2; mt++) {
        #pragma unroll
        for (int nt = 0; nt < 8; nt++) {
            const int row0 = m0 + wm + mt * 16 + (lane >> 2);
            const int col  = n0 + wn + nt * 8 + ((lane & 3) << 1);
            const float bv0 = bias[col];
            const float bv1 = bias[col + 1];
            if (headsplit) {
                const int head = col >> 6, hh = col & 63;
                int bm = row0 >> 9, p = row0 & 511;
                __half2 h0 = __floats2half2_rn(acc[mt][nt][0] + bv0,
                                               acc[mt][nt][1] + bv1);
                *(__half2*)&dsth[((size_t)(bm * NH + head) * PATCH + p) * HS + hh] = h0;
                bm = (row0 + 8) >> 9; p = (row0 + 8) & 511;
                __half2 h1 = __floats2half2_rn(acc[mt][nt][2] + bv0,
                                               acc[mt][nt][3] + bv1);
                *(__half2*)&dsth[((size_t)(bm * NH + head) * PATCH + p) * HS + hh] = h1;
            } else {
                float2 v0, v1;
                v0.x = acc[mt][nt][0] + bv0; v0.y = acc[mt][nt][1] + bv1;
                v1.x = acc[mt][nt][2] + bv0; v1.y = acc[mt][nt][3] + bv1;
                *(float2*)&outf[(size_t)row0 * HID + col] = v0;
                *(float2*)&outf[(size_t)(row0 + 8) * HID + col] = v1;
            }
        }
    }
}

// ---------------------------------------------------------------------------
// fp16 ldmatrix flash attention. 128 threads / 4 warps per (seq, 64-q-tile);
// warp w owns q-rows [16w,16w+16). All tiles 64x64 half, 8 units(16B)/row,
// swizzle u ^ (row&7): every ldsm4/ldsm4t phase and every STS bank-distinct.
// ---------------------------------------------------------------------------
__device__ __forceinline__ void ldtile(uint4* S, const __half* src, int t)
{
    const int r = t >> 1, u0 = (t & 1) * 4;
    const uint4* s4 = (const uint4*)(src + (size_t)r * HS) + u0;
    #pragma unroll
    for (int j = 0; j < 4; j++)
        S[r * 8 + ((u0 + j) ^ (r & 7))] = s4[j];
}

__global__ __launch_bounds__(128, 4)
void attn_h()
{
    __shared__ uint4 Ks[64 * 8];
    __shared__ uint4 Vs[64 * 8];
    __shared__ uint4 Ps[64 * 8];      // Q in prologue, then P (warp-private)

    const int seq = blockIdx.y;
    const int q0  = blockIdx.x * 64;
    const int t    = threadIdx.x;
    const int warp = t >> 5, lane = t & 31;
    const int lq = lane >> 2, lr = lane & 3;

    const __half* qb = g_q16 + ((size_t)seq * PATCH + q0) * HS;
    const __half* kb = g_k16 + (size_t)seq * PATCH * HS;
    const __half* vb = g_v16 + (size_t)seq * PATCH * HS;

    const unsigned ksb = smem_u32(Ks);
    const unsigned vsb = smem_u32(Vs);
    const unsigned psb = smem_u32(Ps);
    const int xrow = (lane & 7) + ((lane >> 3) & 1) * 8;
    const int xhi  = lane >> 4;

    // ---- stage Q (rows are warp-aligned: t>>1 keeps warp w on rows 16w..) ----
    ldtile(Ps, qb, t);
    __syncwarp();

    // ---- Q fragments to registers ----
    const int qrow = warp * 16 + xrow;
    unsigned qf[4][4];
    #pragma unroll
    for (int k8 = 0; k8 < 4; k8++) {
        const unsigned addr = psb +
            ((qrow * 8 + ((k8 * 2 + xhi) ^ (qrow & 7))) << 4);
        ldsm4(qf[k8][0], qf[k8][1], qf[k8][2], qf[k8][3], addr);
    }

    float mA = -1e30f, mB = -1e30f, lA = 0.0f, lB = 0.0f;
    float o[8][4];
    #pragma unroll
    for (int nt = 0; nt < 8; nt++)
        #pragma unroll
        for (int j = 0; j < 4; j++) o[nt][j] = 0.0f;

    ldtile(Ks, kb, t);
    ldtile(Vs, vb, t);
    __syncthreads();

    const int rA = warp * 16 + lq;
    __half2* Ph = (__half2*)Ps;

    for (int jt = 0; jt < 8; jt++) {
        // ---- S = Q K^T ----
        float s[8][4];
        #pragma unroll
        for (int nt = 0; nt < 8; nt++)
            #pragma unroll
            for (int j = 0; j < 4; j++) s[nt][j] = 0.0f;

        #pragma unroll
        for (int k8 = 0; k8 < 4; k8++) {
            #pragma unroll
            for (int ntq = 0; ntq < 4; ntq++) {
                const int row = ntq * 16 + xrow;
                const unsigned addr = ksb +
                    ((row * 8 + ((k8 * 2 + xhi) ^ (row & 7))) << 4);
                unsigned r0, r1, r2, r3;
                ldsm4(r0, r1, r2, r3, addr);
                unsigned b0[2] = {r0, r2};
                unsigned b1[2] = {r1, r3};
                mma16816(s[ntq * 2],     qf[k8], b0);
                mma16816(s[ntq * 2 + 1], qf[k8], b1);
            }
        }
        #pragma unroll
        for (int nt = 0; nt < 8; nt++)
            #pragma unroll
            for (int j = 0; j < 4; j++) s[nt][j] *= 0.125f;

        // ---- online softmax (rows A=rA, B=rA+8) ----
        float tA = -1e30f, tB = -1e30f;
        #pragma unroll
        for (int nt = 0; nt < 8; nt++) {
            tA = fmaxf(tA, fmaxf(s[nt][0], s[nt][1]));
            tB = fmaxf(tB, fmaxf(s[nt][2], s[nt][3]));
        }
        tA = fmaxf(tA, __shfl_xor_sync(0xffffffffu, tA, 1));
        tA = fmaxf(tA, __shfl_xor_sync(0xffffffffu, tA, 2));
        tB = fmaxf(tB, __shfl_xor_sync(0xffffffffu, tB, 1));
        tB = fmaxf(tB, __shfl_xor_sync(0xffffffffu, tB, 2));
        const float nmA = fmaxf(mA, tA), nmB = fmaxf(mB, tB);
        const float fA = __expf(mA - nmA), fB = __expf(mB - nmB);
        mA = nmA; mB = nmB;

        float sumA = 0.0f, sumB = 0.0f;
        #pragma unroll
        for (int nt = 0; nt < 8; nt++) {
            const float p0 = __expf(s[nt][0] - mA);
            const float p1 = __expf(s[nt][1] - mA);
            const float p2 = __expf(s[nt][2] - mB);
            const float p3 = __expf(s[nt][3] - mB);
            sumA += p0 + p1;
            sumB += p2 + p3;
            Ph[rA * 32 + ((nt ^ (rA & 7)) << 2) + lr] = __floats2half2_rn(p0, p1);
            Ph[(rA + 8) * 32 + ((nt ^ ((rA + 8) & 7)) << 2) + lr] =
                __floats2half2_rn(p2, p3);
        }
        sumA += __shfl_xor_sync(0xffffffffu, sumA, 1);
        sumA += __shfl_xor_sync(0xffffffffu, sumA, 2);
        sumB += __shfl_xor_sync(0xffffffffu, sumB, 1);
        sumB += __shfl_xor_sync(0xffffffffu, sumB, 2);
        lA = lA * fA + sumA;
        lB = lB * fB + sumB;
        #pragma unroll
        for (int nt = 0; nt < 8; nt++) {
            o[nt][0] *= fA; o[nt][1] *= fA;
            o[nt][2] *= fB; o[nt][3] *= fB;
        }
        __syncwarp();

        // ---- O += P V ----
        #pragma unroll
        for (int k8 = 0; k8 < 4; k8++) {
            unsigned a[4];
            {
                const unsigned addr = psb +
                    ((qrow * 8 + ((k8 * 2 + xhi) ^ (qrow & 7))) << 4);
                ldsm4(a[0], a[1], a[2], a[3], addr);
            }
            #pragma unroll
            for (int ntp = 0; ntp < 8; ntp += 2) {
                const int vrow = k8 * 16 + xrow;
                const unsigned addr = vsb +
                    ((vrow * 8 + ((ntp + xhi) ^ (vrow & 7))) << 4);
                unsigned r0, r1, r2, r3;
                ldsm4t(r0, r1, r2, r3, addr);
                unsigned b0[2] = {r0, r1};
                unsigned b1[2] = {r2, r3};
                mma16816(o[ntp],     a, b0);
                mma16816(o[ntp + 1], a, b1);
            }
        }

        if (jt < 7) {
            __syncthreads();
            ldtile(Ks, kb + (size_t)(jt + 1) * 64 * HS, t);
            ldtile(Vs, vb + (size_t)(jt + 1) * 64 * HS, t);
            __syncthreads();
        }
    }

    // ---- epilogue: normalize, write merged-head ctx (fp16) ----
    const float invA = 1.0f / lA, invB = 1.0f / lB;
    const int bm = seq / NH, head = seq % NH;
    const int rowA = bm * PATCH + q0 + rA;
    __half* dA = g_c16 + (size_t)rowA * HID + head * HS;
    __half* dB = dA + (size_t)8 * HID;
    #pragma unroll
    for (int nt = 0; nt < 8; nt++) {
        *(__half2*)&dA[nt * 8 + 2 * lr] =
            __floats2half2_rn(o[nt][0] * invA, o[nt][1] * invA);
        *(__half2*)&dB[nt * 8 + 2 * lr] =
            __floats2half2_rn(o[nt][2] * invB, o[nt][3] * invB);
    }
}

// ---------------------------------------------------------------------------
extern "C" void kernel_launch(void* const* d_in, const int* in_sizes, int n_in,
                              void* d_out, int out_size)
{
    const float* hs = (const float*)d_in[0];
    const float* Wq = (const float*)d_in[1];
    const float* bq = (const float*)d_in[2];
    const float* Wk = (const float*)d_in[3];
    const float* bk = (const float*)d_in[4];
    const float* Wv = (const float*)d_in[5];
    const float* bv = (const float*)d_in[6];
    const float* Wo = (const float*)d_in[7];
    const float* bo = (const float*)d_in[8];
    float* out = (float*)d_out;

    cvt_all<<<(ROWS * HID / 4 + 255) / 256, 256>>>(hs, Wq, Wk, Wv, Wo);
    h16_gemm<<<dim3(128, 6, 3), 256>>>(bq, bk, bv, bo, nullptr, 1);
    attn_h<<<dim3(8, 384), 128>>>();
    h16_gemm<<<dim3(128, 6, 1), 256>>>(bq, bk, bv, bo, out, 0);
}

// round 8
// speedup vs baseline: 7.1189x; 1.2122x over previous
#include <cuda_runtime.h>
#include <cuda_fp16.h>
#include <cstdint>

#define HID 768
#define NH 12
#define HS 64
#define PATCH 512
#define ROWS 16384
#define BK 32

// fp16 scratch (device globals: the allowed no-alloc path)
__device__ __half g_h16[ROWS * HID];
__device__ __half g_w16[4][HID * HID];
__device__ __half g_q16[ROWS * HID];
__device__ __half g_k16[ROWS * HID];
__device__ __half g_v16[ROWS * HID];
__device__ __half g_c16[ROWS * HID];

// ---------------------------------------------------------------------------
// helpers
// ---------------------------------------------------------------------------
__device__ __forceinline__ void mma16816(float c[4],
                                         const unsigned a[4],
                                         const unsigned b[2]) {
    asm volatile(
        "mma.sync.aligned.m16n8k16.row.col.f32.f16.f16.f32 "
        "{%0,%1,%2,%3},{%4,%5,%6,%7},{%8,%9},{%0,%1,%2,%3};"
        : "+f"(c[0]), "+f"(c[1]), "+f"(c[2]), "+f"(c[3])
        : "r"(a[0]), "r"(a[1]), "r"(a[2]), "r"(a[3]), "r"(b[0]), "r"(b[1]));
}

__device__ __forceinline__ unsigned smem_u32(const void* p) {
    return (unsigned)__cvta_generic_to_shared(p);
}

__device__ __forceinline__ void ldsm4(unsigned& r0, unsigned& r1,
                                      unsigned& r2, unsigned& r3,
                                      unsigned addr) {
    asm volatile(
        "ldmatrix.sync.aligned.m8n8.x4.shared.b16 {%0,%1,%2,%3},[%4];"
        : "=r"(r0), "=r"(r1), "=r"(r2), "=r"(r3) : "r"(addr));
}

__device__ __forceinline__ void ldsm4t(unsigned& r0, unsigned& r1,
                                       unsigned& r2, unsigned& r3,
                                       unsigned addr) {
    asm volatile(
        "ldmatrix.sync.aligned.m8n8.x4.trans.shared.b16 {%0,%1,%2,%3},[%4];"
        : "=r"(r0), "=r"(r1), "=r"(r2), "=r"(r3) : "r"(addr));
}

__device__ __forceinline__ void cp16(unsigned dst, const void* src) {
    asm volatile("cp.async.cg.shared.global [%0], [%1], 16;"
                 :: "r"(dst), "l"(src) : "memory");
}
__device__ __forceinline__ void cp_commit() {
    asm volatile("cp.async.commit_group;" ::: "memory");
}
template <int N>
__device__ __forceinline__ void cp_wait() {
    asm volatile("cp.async.wait_group %0;" :: "n"(N) : "memory");
}

// ---------------------------------------------------------------------------
// Prologue: convert hidden + 4 weight matrices to fp16 (single launch)
// ---------------------------------------------------------------------------
__global__ void cvt_all(const float* __restrict__ hs,
                        const float* __restrict__ Wq,
                        const float* __restrict__ Wk,
                        const float* __restrict__ Wv,
                        const float* __restrict__ Wo)
{
    const int i = blockIdx.x * blockDim.x + threadIdx.x;   // float4 index
    const int nh4 = ROWS * HID / 4;
    if (i < nh4) {
        float4 v = ((const float4*)hs)[i];
        __half2 h0 = __floats2half2_rn(v.x, v.y);
        __half2 h1 = __floats2half2_rn(v.z, v.w);
        uint2 u; u.x = *(unsigned*)&h0; u.y = *(unsigned*)&h1;
        ((uint2*)g_h16)[i] = u;
    }
    const int nw4 = HID * HID / 4;
    if (i < nw4) {
        const float* srcs[4] = {Wq, Wk, Wv, Wo};
        #pragma unroll
        for (int z = 0; z < 4; z++) {
            float4 v = ((const float4*)srcs[z])[i];
            __half2 h0 = __floats2half2_rn(v.x, v.y);
            __half2 h1 = __floats2half2_rn(v.z, v.w);
            uint2 u; u.x = *(unsigned*)&h0; u.y = *(unsigned*)&h1;
            ((uint2*)g_w16[z])[i] = u;
        }
    }
}

// ---------------------------------------------------------------------------
// fp16 GEMM with cp.async 4-stage pipeline: out = A16 @ W16 + b
// 128x128x32 tiles, 8 warps (4x2), warp tile 32x64, m16n8k16, ldmatrix frags.
// Stage (16KB): A 128rows x 32half swizzled (8KB) + B 32k x 128n (8KB).
// ---------------------------------------------------------------------------
#define NSTAGE 4
#define STG_BYTES 16384
#define GEMM_SMEM (NSTAGE * STG_BYTES)    // 64 KB dynamic

__global__ __launch_bounds__(256, 2)
void h16_gemm(const float* __restrict__ bq, const float* __restrict__ bk,
              const float* __restrict__ bv, const float* __restrict__ bo,
              float* __restrict__ outf, int headsplit)
{
    extern __shared__ char dsm[];
    const unsigned sbase = smem_u32(dsm);

    const int z = blockIdx.z;
    const __half* A = headsplit ? g_h16 : g_c16;
    const __half* W = g_w16[headsplit ? z : 3];
    const float* bias = headsplit ? (z == 0 ? bq : z == 1 ? bk : bv) : bo;
    __half* dsth = (z == 0) ? g_q16 : (z == 1) ? g_k16 : g_v16;

    const int m0 = blockIdx.x * 128;
    const int n0 = blockIdx.y * 128;
    const int t = threadIdx.x;
    const int warp = t >> 5, lane = t & 31;
    const int wm = (warp & 3) * 32;
    const int wn = (warp >> 2) * 64;
    const int wn8 = wn >> 3;

    // ---- staging mapping (4x cp16 per thread per stage) ----
    const int ar   = t >> 1;                 // A row 0..127
    const int aku  = (t & 1) * 2;            // first of 2 k-units
    const int asr  = ar >> 1;
    const int abse = (ar & 1) * 4;
    const unsigned aoff0 = (unsigned)(asr * 8 + ((abse + aku) ^ (asr & 7))) * 16;
    const unsigned aoff1 = (unsigned)(asr * 8 + ((abse + aku + 1) ^ (asr & 7))) * 16;
    const __half* Ap = A + (size_t)(m0 + ar) * HID + aku * 8;

    const int bkr  = t >> 3;                 // B k-row 0..31
    const int bun  = (t & 7) * 2;
    const unsigned boff0 = 8192 + (unsigned)(bkr * 16 + (bun ^ (bkr & 7))) * 16;
    const unsigned boff1 = 8192 + (unsigned)(bkr * 16 + ((bun + 1) ^ (bkr & 7))) * 16;
    const __half* Wp = W + (size_t)bkr * HID + n0 + bun * 8;

    // ---- ldmatrix lane components ----
    const int a_m   = wm + (lane & 7) + ((lane >> 3) & 1) * 8;
    const int a_sr  = a_m >> 1;
    const int a_sw  = a_sr & 7;
    const int a_bse = (a_m & 1) * 4;
    const int a_hi  = lane >> 4;
    const int b_krow = (lane & 7) + ((lane >> 3) & 1) * 8;
    const int b_hi   = lane >> 4;
    const int b_sw   = lane & 7;

    float acc[2][8][4];
    #pragma unroll
    for (int i = 0; i < 2; i++)
        #pragma unroll
        for (int j = 0; j < 8; j++)
            #pragma unroll
            for (int l = 0; l < 4; l++) acc[i][j][l] = 0.0f;

    const int NIT = HID / BK;      // 24

    // ---- prologue: issue stages 0..NSTAGE-2 ----
    #pragma unroll
    for (int s = 0; s < NSTAGE - 1; s++) {
        const unsigned sb = sbase + s * STG_BYTES;
        const __half* Ac = Ap + s * BK;
        const __half* Wc = Wp + (size_t)s * BK * HID;
        cp16(sb + aoff0, Ac);
        cp16(sb + aoff1, Ac + 8);
        cp16(sb + boff0, Wc);
        cp16(sb + boff1, Wc + 8);
        cp_commit();
    }

    int buf = 0;
    for (int it = 0; it < NIT; ++it) {
        cp_wait<NSTAGE - 2>();
        __syncthreads();

        // issue chunk it+NSTAGE-1 into slot (it-1)%NSTAGE (consumed last iter)
        const int cnext = it + NSTAGE - 1;
        if (cnext < NIT) {
            const unsigned sb = sbase + (cnext % NSTAGE) * STG_BYTES;
            const __half* Ac = Ap + cnext * BK;
            const __half* Wc = Wp + (size_t)cnext * BK * HID;
            cp16(sb + aoff0, Ac);
            cp16(sb + aoff1, Ac + 8);
            cp16(sb + boff0, Wc);
            cp16(sb + boff1, Wc + 8);
        }
        cp_commit();

        const unsigned abuf = sbase + buf * STG_BYTES;
        const unsigned bbuf = abuf + 8192;

        #pragma unroll
        for (int s = 0; s < 2; s++) {
            unsigned af[2][4];
            #pragma unroll
            for (int mt = 0; mt < 2; mt++) {
                const int sr = a_sr + mt * 8;
                const unsigned addr = abuf +
                    ((sr * 8 + ((a_bse + s * 2 + a_hi) ^ a_sw)) << 4);
                ldsm4(af[mt][0], af[mt][1], af[mt][2], af[mt][3], addr);
            }
            unsigned bf[8][2];
            #pragma unroll
            for (int ntp = 0; ntp < 8; ntp += 2) {
                const int row = s * 16 + b_krow;
                const unsigned addr = bbuf +
                    ((row * 16 + ((wn8 + ntp + b_hi) ^ b_sw)) << 4);
                ldsm4t(bf[ntp][0], bf[ntp][1], bf[ntp + 1][0], bf[ntp + 1][1],
                       addr);
            }
            #pragma unroll
            for (int mt = 0; mt < 2; mt++)
                #pragma unroll
                for (int nt = 0; nt < 8; nt++)
                    mma16816(acc[mt][nt], af[mt], bf[nt]);
        }

        buf = (buf + 1) & (NSTAGE - 1);
    }

    // ---- epilogue ----
    #pragma unroll
    for (int mt = 0; mt < 2; mt++) {
        #pragma unroll
        for (int nt = 0; nt < 8; nt++) {
            const int row0 = m0 + wm + mt * 16 + (lane >> 2);
            const int col  = n0 + wn + nt * 8 + ((lane & 3) << 1);
            const float bv0 = bias[col];
            const float bv1 = bias[col + 1];
            if (headsplit) {
                const int head = col >> 6, hh = col & 63;
                int bm = row0 >> 9, p = row0 & 511;
                __half2 h0 = __floats2half2_rn(acc[mt][nt][0] + bv0,
                                               acc[mt][nt][1] + bv1);
                *(__half2*)&dsth[((size_t)(bm * NH + head) * PATCH + p) * HS + hh] = h0;
                bm = (row0 + 8) >> 9; p = (row0 + 8) & 511;
                __half2 h1 = __floats2half2_rn(acc[mt][nt][2] + bv0,
                                               acc[mt][nt][3] + bv1);
                *(__half2*)&dsth[((size_t)(bm * NH + head) * PATCH + p) * HS + hh] = h1;
            } else {
                float2 v0, v1;
                v0.x = acc[mt][nt][0] + bv0; v0.y = acc[mt][nt][1] + bv1;
                v1.x = acc[mt][nt][2] + bv0; v1.y = acc[mt][nt][3] + bv1;
                *(float2*)&outf[(size_t)row0 * HID + col] = v0;
                *(float2*)&outf[(size_t)(row0 + 8) * HID + col] = v1;
            }
        }
    }
}

// ---------------------------------------------------------------------------
// fp16 ldmatrix flash attention with cp.async double-buffered K/V.
// 128 threads / 4 warps per (seq, 64-q-tile); warp w owns q-rows [16w,16w+16).
// Tiles 64x64 half, 8 units(16B)/row, swizzle u ^ (row&7).
// ---------------------------------------------------------------------------
__device__ __forceinline__ void cptile(unsigned sbase, const __half* src, int t)
{
    const int r = t >> 1, u0 = (t & 1) * 4;
    const __half* s = src + (size_t)r * HS + u0 * 8;
    #pragma unroll
    for (int j = 0; j < 4; j++)
        cp16(sbase + ((r * 8 + ((u0 + j) ^ (r & 7))) << 4), s + 8 * j);
}

__global__ __launch_bounds__(128, 4)
void attn_h()
{
    __shared__ uint4 Kb[2][64 * 8];
    __shared__ uint4 Vb[2][64 * 8];
    __shared__ uint4 Ps[64 * 8];

    const int seq = blockIdx.y;
    const int q0  = blockIdx.x * 64;
    const int t    = threadIdx.x;
    const int warp = t >> 5, lane = t & 31;
    const int lq = lane >> 2, lr = lane & 3;

    const __half* qb = g_q16 + ((size_t)seq * PATCH + q0) * HS;
    const __half* kb = g_k16 + (size_t)seq * PATCH * HS;
    const __half* vb = g_v16 + (size_t)seq * PATCH * HS;

    const unsigned k0b = smem_u32(Kb[0]);
    const unsigned v0b = smem_u32(Vb[0]);
    const unsigned psb = smem_u32(Ps);
    const int xrow = (lane & 7) + ((lane >> 3) & 1) * 8;
    const int xhi  = lane >> 4;

    // prefetch tile 0
    cptile(k0b, kb, t);
    cptile(v0b, vb, t);
    cp_commit();

    // stage Q (regular stores; t>>1 keeps warp w on its own 16 rows)
    {
        const int r = t >> 1, u0 = (t & 1) * 4;
        const uint4* s4 = (const uint4*)(qb + (size_t)r * HS) + u0;
        #pragma unroll
        for (int j = 0; j < 4; j++)
            Ps[r * 8 + ((u0 + j) ^ (r & 7))] = s4[j];
    }
    __syncwarp();

    const int qrow = warp * 16 + xrow;
    unsigned qf[4][4];
    #pragma unroll
    for (int k8 = 0; k8 < 4; k8++) {
        const unsigned addr = psb +
            ((qrow * 8 + ((k8 * 2 + xhi) ^ (qrow & 7))) << 4);
        ldsm4(qf[k8][0], qf[k8][1], qf[k8][2], qf[k8][3], addr);
    }

    float mA = -1e30f, mB = -1e30f, lA = 0.0f, lB = 0.0f;
    float o[8][4];
    #pragma unroll
    for (int nt = 0; nt < 8; nt++)
        #pragma unroll
        for (int j = 0; j < 4; j++) o[nt][j] = 0.0f;

    const int rA = warp * 16 + lq;
    __half2* Ph = (__half2*)Ps;

    for (int jt = 0; jt < 8; jt++) {
        cp_wait<0>();
        __syncthreads();

        // stream next tile into the other buffer during this tile's compute
        if (jt < 7) {
            const int nb = (jt + 1) & 1;
            cptile(smem_u32(Kb[nb]), kb + (size_t)(jt + 1) * 64 * HS, t);
            cptile(smem_u32(Vb[nb]), vb + (size_t)(jt + 1) * 64 * HS, t);
        }
        cp_commit();

        const unsigned ksb = smem_u32(Kb[jt & 1]);
        const unsigned vsb = smem_u32(Vb[jt & 1]);

        // ---- S = Q K^T ----
        float s[8][4];
        #pragma unroll
        for (int nt = 0; nt < 8; nt++)
            #pragma unroll
            for (int j = 0; j < 4; j++) s[nt][j] = 0.0f;

        #pragma unroll
        for (int k8 = 0; k8 < 4; k8++) {
            #pragma unroll
            for (int ntq = 0; ntq < 4; ntq++) {
                const int row = ntq * 16 + xrow;
                const unsigned addr = ksb +
                    ((row * 8 + ((k8 * 2 + xhi) ^ (row & 7))) << 4);
                unsigned r0, r1, r2, r3;
                ldsm4(r0, r1, r2, r3, addr);
                unsigned b0[2] = {r0, r2};
                unsigned b1[2] = {r1, r3};
                mma16816(s[ntq * 2],     qf[k8], b0);
                mma16816(s[ntq * 2 + 1], qf[k8], b1);
            }
        }
        #pragma unroll
        for (int nt = 0; nt < 8; nt++)
            #pragma unroll
            for (int j = 0; j < 4; j++) s[nt][j] *= 0.125f;

        // ---- online softmax ----
        float tA = -1e30f, tB = -1e30f;
        #pragma unroll
        for (int nt = 0; nt < 8; nt++) {
            tA = fmaxf(tA, fmaxf(s[nt][0], s[nt][1]));
            tB = fmaxf(tB, fmaxf(s[nt][2], s[nt][3]));
        }
        tA = fmaxf(tA, __shfl_xor_sync(0xffffffffu, tA, 1));
        tA = fmaxf(tA, __shfl_xor_sync(0xffffffffu, tA, 2));
        tB = fmaxf(tB, __shfl_xor_sync(0xffffffffu, tB, 1));
        tB = fmaxf(tB, __shfl_xor_sync(0xffffffffu, tB, 2));
        const float nmA = fmaxf(mA, tA), nmB = fmaxf(mB, tB);
        const float fA = __expf(mA - nmA), fB = __expf(mB - nmB);
        mA = nmA; mB = nmB;

        float sumA = 0.0f, sumB = 0.0f;
        #pragma unroll
        for (int nt = 0; nt < 8; nt++) {
            const float p0 = __expf(s[nt][0] - mA);
            const float p1 = __expf(s[nt][1] - mA);
            const float p2 = __expf(s[nt][2] - mB);
            const float p3 = __expf(s[nt][3] - mB);
            sumA += p0 + p1;
            sumB += p2 + p3;
            Ph[rA * 32 + ((nt ^ (rA & 7)) << 2) + lr] = __floats2half2_rn(p0, p1);
            Ph[(rA + 8) * 32 + ((nt ^ ((rA + 8) & 7)) << 2) + lr] =
                __floats2half2_rn(p2, p3);
        }
        sumA += __shfl_xor_sync(0xffffffffu, sumA, 1);
        sumA += __shfl_xor_sync(0xffffffffu, sumA, 2);
        sumB += __shfl_xor_sync(0xffffffffu, sumB, 1);
        sumB += __shfl_xor_sync(0xffffffffu, sumB, 2);
        lA = lA * fA + sumA;
        lB = lB * fB + sumB;
        #pragma unroll
        for (int nt = 0; nt < 8; nt++) {
            o[nt][0] *= fA; o[nt][1] *= fA;
            o[nt][2] *= fB; o[nt][3] *= fB;
        }
        __syncwarp();

        // ---- O += P V ----
        #pragma unroll
        for (int k8 = 0; k8 < 4; k8++) {
            unsigned a[4];
            {
                const unsigned addr = psb +
                    ((qrow * 8 + ((k8 * 2 + xhi) ^ (qrow & 7))) << 4);
                ldsm4(a[0], a[1], a[2], a[3], addr);
            }
            #pragma unroll
            for (int ntp = 0; ntp < 8; ntp += 2) {
                const int vrow = k8 * 16 + xrow;
                const unsigned addr = vsb +
                    ((vrow * 8 + ((ntp + xhi) ^ (vrow & 7))) << 4);
                unsigned r0, r1, r2, r3;
                ldsm4t(r0, r1, r2, r3, addr);
                unsigned b0[2] = {r0, r1};
                unsigned b1[2] = {r2, r3};
                mma16816(o[ntp],     a, b0);
                mma16816(o[ntp + 1], a, b1);
            }
        }
    }

    // ---- epilogue: normalize, write merged-head ctx (fp16) ----
    const float invA = 1.0f / lA, invB = 1.0f / lB;
    const int bm = seq / NH, head = seq % NH;
    const int rowA = bm * PATCH + q0 + rA;
    __half* dA = g_c16 + (size_t)rowA * HID + head * HS;
    __half* dB = dA + (size_t)8 * HID;
    #pragma unroll
    for (int nt = 0; nt < 8; nt++) {
        *(__half2*)&dA[nt * 8 + 2 * lr] =
            __floats2half2_rn(o[nt][0] * invA, o[nt][1] * invA);
        *(__half2*)&dB[nt * 8 + 2 * lr] =
            __floats2half2_rn(o[nt][2] * invB, o[nt][3] * invB);
    }
}

// ---------------------------------------------------------------------------
extern "C" void kernel_launch(void* const* d_in, const int* in_sizes, int n_in,
                              void* d_out, int out_size)
{
    const float* hs = (const float*)d_in[0];
    const float* Wq = (const float*)d_in[1];
    const float* bq = (const float*)d_in[2];
    const float* Wk = (const float*)d_in[3];
    const float* bk = (const float*)d_in[4];
    const float* Wv = (const float*)d_in[5];
    const float* bv = (const float*)d_in[6];
    const float* Wo = (const float*)d_in[7];
    const float* bo = (const float*)d_in[8];
    float* out = (float*)d_out;

    cudaFuncSetAttribute(h16_gemm,
                         cudaFuncAttributeMaxDynamicSharedMemorySize, GEMM_SMEM);

    cvt_all<<<(ROWS * HID / 4 + 255) / 256, 256>>>(hs, Wq, Wk, Wv, Wo);
    h16_gemm<<<dim3(128, 6, 3), 256, GEMM_SMEM>>>(bq, bk, bv, bo, nullptr, 1);
    attn_h<<<dim3(8, 384), 128>>>();
    h16_gemm<<<dim3(128, 6, 1), 256, GEMM_SMEM>>>(bq, bk, bv, bo, out, 0);
}